// round 4
// baseline (speedup 1.0000x reference)
#include <cuda_runtime.h>
#include <math.h>

#define NB 32
#define WTOT 202112

// Scratch (device globals — no allocations allowed)
__device__ float g_y[NB * WTOT];          // generated per-sample conv weights, ~25.9 MB
__device__ float g_A[NB * 1048576];       // ping buffer, 128 MB
__device__ float g_B[NB * 1048576];       // pong buffer, 128 MB
__device__ float g_stats[NB * 64 * 2];    // per-(b,c) BN scale/shift

// ---- packed f32x2 helpers (FFMA2 only reachable via PTX) -------------------
__device__ __forceinline__ unsigned long long pack2(float lo, float hi) {
    unsigned long long r;
    asm("mov.b64 %0, {%1, %2};" : "=l"(r) : "f"(lo), "f"(hi));
    return r;
}
__device__ __forceinline__ void ffma2(unsigned long long& d,
                                      unsigned long long a, unsigned long long b) {
    asm("fma.rn.f32x2 %0, %1, %2, %0;" : "+l"(d) : "l"(a), "l"(b));
}
__device__ __forceinline__ void unpack2(unsigned long long v, float& lo, float& hi) {
    asm("mov.b64 {%0, %1}, %2;" : "=f"(lo), "=f"(hi) : "l"(v));
}

// ---------------------------------------------------------------------------
// Weight generation: y[s][r] = W[r,:] @ a[s,:] + b[r]
// ---------------------------------------------------------------------------
__global__ void gen_weights(const float* __restrict__ W, const float* __restrict__ bias,
                            const float* __restrict__ act, int rows, int off) {
    __shared__ float sa[NB * 32];
    for (int i = threadIdx.x; i < NB * 32; i += blockDim.x) sa[i] = act[i];
    __syncthreads();
    int r = blockIdx.x * blockDim.x + threadIdx.x;
    if (r >= rows) return;
    float w[32];
    const float4* wp = reinterpret_cast<const float4*>(W + (size_t)r * 32);
#pragma unroll
    for (int i = 0; i < 8; i++) {
        float4 v = wp[i];
        w[4*i+0] = v.x; w[4*i+1] = v.y; w[4*i+2] = v.z; w[4*i+3] = v.w;
    }
    float bv = bias[r];
    for (int s = 0; s < NB; s++) {
        float acc = bv;
#pragma unroll
        for (int k = 0; k < 32; k++) acc = fmaf(w[k], sa[s*32+k], acc);
        g_y[(size_t)s * WTOT + off + r] = acc;
    }
}

// ---------------------------------------------------------------------------
// BN stats: one block per (b,c) plane -> scale = g*rsqrt(var+eps),
// shift = be - mean*scale (training-mode BN, biased variance).
// ---------------------------------------------------------------------------
__global__ void bn_stats(const float* __restrict__ src, const float* __restrict__ g,
                         const float* __restrict__ be, int C, int HW) {
    int plane = blockIdx.x;
    int c = plane % C;
    const float* p = src + (size_t)plane * HW;
    float s = 0.f, s2 = 0.f;
    for (int i = threadIdx.x; i < HW; i += 256) { float v = p[i]; s += v; s2 = fmaf(v, v, s2); }
    __shared__ float sh0[256], sh1[256];
    sh0[threadIdx.x] = s; sh1[threadIdx.x] = s2;
    __syncthreads();
    for (int ofs = 128; ofs > 0; ofs >>= 1) {
        if (threadIdx.x < ofs) {
            sh0[threadIdx.x] += sh0[threadIdx.x + ofs];
            sh1[threadIdx.x] += sh1[threadIdx.x + ofs];
        }
        __syncthreads();
    }
    if (threadIdx.x == 0) {
        float inv = 1.f / (float)HW;
        float m = sh0[0] * inv;
        float var = sh1[0] * inv - m * m;
        float sc = g[c] * rsqrtf(var + 1e-5f);
        g_stats[plane*2]   = sc;
        g_stats[plane*2+1] = be[c] - m * sc;
    }
}

// ---------------------------------------------------------------------------
// Direct 5x5 conv, dilation DIL, pad = 2*DIL, BN(+relu) folded into tile load.
// 32x32 output tile / 16 channels per block; packed FFMA2 inner loop:
// acc paired across adjacent output channels, weight pairs via broadcast LDS.64.
// ---------------------------------------------------------------------------
template<int DIL, int MODE>
__global__ __launch_bounds__(256)
void conv5x5(const float* __restrict__ in, float* __restrict__ out,
             int Cin, int S, int wOff, int grps) {
    constexpr int PAD = 2 * DIL;
    constexpr int TIN = 32 + 4 * DIL;
    constexpr int RS  = 48;
    __shared__ float sm[TIN * RS];
    __shared__ __align__(8) float sw[25 * 16];    // [wk][gg] layout
    int z = blockIdx.z;
    int b = z / grps, gq = z - b * grps;
    int gbase = gq * 16;
    int x0 = blockIdx.x * 32, y0 = blockIdx.y * 32;
    int tx = threadIdx.x, ty = threadIdx.y;
    int tid = ty * 16 + tx;
    unsigned long long acc[4][8];
#pragma unroll
    for (int p = 0; p < 4; p++)
#pragma unroll
        for (int j = 0; j < 8; j++) acc[p][j] = 0ULL;
    const float* wb = g_y + (size_t)b * WTOT + wOff;

    for (int c = 0; c < Cin; c++) {
        float sc = 1.f, sf = 0.f;
        if (MODE) { sc = g_stats[(b*Cin+c)*2]; sf = g_stats[(b*Cin+c)*2+1]; }
        const float* ip = in + ((size_t)(b * Cin + c)) * S * S;
        for (int i = tid; i < TIN * TIN; i += 256) {
            int r = i / TIN, col = i - r * TIN;
            int iy = y0 - PAD + r, ix = x0 - PAD + col;
            float v = 0.f;
            if (iy >= 0 && iy < S && ix >= 0 && ix < S) {
                v = ip[(size_t)iy * S + ix];
                if (MODE) { v = fmaf(v, sc, sf); if (MODE == 2) v = fmaxf(v, 0.f); }
            }
            sm[r * RS + col] = v;
        }
        // weights: sw[k*16 + gg]
        for (int i = tid; i < 400; i += 256) {
            int k = i >> 4, gg = i & 15;
            sw[i] = wb[((size_t)(gbase + gg) * Cin + c) * 25 + k];
        }
        __syncthreads();
#pragma unroll 1
        for (int ky = 0; ky < 5; ky++) {
#pragma unroll
            for (int kx = 0; kx < 5; kx++) {
                int base = (ty + ky * DIL) * RS + tx + kx * DIL;
                unsigned long long T0 = pack2(sm[base],                sm[base]);
                unsigned long long T1 = pack2(sm[base + 16],           sm[base + 16]);
                unsigned long long T2 = pack2(sm[base + 16*RS],        sm[base + 16*RS]);
                unsigned long long T3 = pack2(sm[base + 16*RS + 16],   sm[base + 16*RS + 16]);
                const unsigned long long* wq =
                    reinterpret_cast<const unsigned long long*>(sw + (ky * 5 + kx) * 16);
#pragma unroll
                for (int j = 0; j < 8; j++) {
                    unsigned long long w2 = wq[j];     // broadcast LDS.64: (w[2j], w[2j+1])
                    ffma2(acc[0][j], T0, w2);
                    ffma2(acc[1][j], T1, w2);
                    ffma2(acc[2][j], T2, w2);
                    ffma2(acc[3][j], T3, w2);
                }
            }
        }
        __syncthreads();
    }
    int Cout = grps * 16;
#pragma unroll
    for (int j = 0; j < 8; j++) {
        float e0, e1;
        float* op0 = out + ((size_t)(b * Cout + gbase + 2*j)) * S * S;
        float* op1 = op0 + (size_t)S * S;
        size_t o00 = (size_t)(y0 + ty) * S + x0 + tx;
        size_t o10 = (size_t)(y0 + ty + 16) * S + x0 + tx;
        unpack2(acc[0][j], e0, e1); op0[o00]      = e0; op1[o00]      = e1;
        unpack2(acc[1][j], e0, e1); op0[o00 + 16] = e0; op1[o00 + 16] = e1;
        unpack2(acc[2][j], e0, e1); op0[o10]      = e0; op1[o10]      = e1;
        unpack2(acc[3][j], e0, e1); op0[o10 + 16] = e0; op1[o10 + 16] = e1;
    }
}

// ---------------------------------------------------------------------------
// 2x2 avg-pool fused with BN-apply (affine commutes with mean).
// ---------------------------------------------------------------------------
__global__ void pool_bn(const float* __restrict__ in, float* __restrict__ out) {
    int idx = blockIdx.x * blockDim.x + threadIdx.x;
    if (idx >= NB * 16 * 128 * 128) return;
    int x = idx & 127, y = (idx >> 7) & 127, pc = idx >> 14;
    const float* ip = in + (size_t)pc * 65536;
    int o2 = (2 * y) * 256 + 2 * x;
    float v = (ip[o2] + ip[o2+1] + ip[o2+256] + ip[o2+257]) * 0.25f;
    out[idx] = fmaf(v, g_stats[pc*2], g_stats[pc*2+1]);
}

// ---------------------------------------------------------------------------
// 1x1 conv (64 -> 8) with BN(stats6) folded into input.
// ---------------------------------------------------------------------------
__global__ void conv1x1(const float* __restrict__ in, float* __restrict__ out) {
    __shared__ float sw[512];
    int b = blockIdx.y;
    const float* wb = g_y + (size_t)b * WTOT + 201600;
    for (int i = threadIdx.x; i < 512; i += blockDim.x) sw[i] = wb[i];
    __syncthreads();
    int pix = blockIdx.x * blockDim.x + threadIdx.x;
    if (pix >= 16384) return;
    float acc[8] = {0,0,0,0,0,0,0,0};
    for (int c = 0; c < 64; c++) {
        float v = in[((size_t)(b*64 + c)) * 16384 + pix];
        v = fmaf(v, g_stats[(b*64+c)*2], g_stats[(b*64+c)*2+1]);
#pragma unroll
        for (int o = 0; o < 8; o++) acc[o] = fmaf(v, sw[o*64 + c], acc[o]);
    }
#pragma unroll
    for (int o = 0; o < 8; o++) out[((size_t)(b*8 + o)) * 16384 + pix] = acc[o];
}

// ---------------------------------------------------------------------------
// Bilinear x2 upsample (align_corners=True) + channel softmax (C=8).
// ---------------------------------------------------------------------------
__global__ void up_softmax(const float* __restrict__ in, float* __restrict__ out) {
    int idx = blockIdx.x * blockDim.x + threadIdx.x;
    if (idx >= NB * 65536) return;
    int x = idx & 255, y = (idx >> 8) & 255, b = idx >> 16;
    const float r = 127.0f / 255.0f;
    float sy = y * r, sx = x * r;
    int y0 = (int)sy, x0 = (int)sx;
    int y1 = min(y0 + 1, 127), x1 = min(x0 + 1, 127);
    float wy = sy - (float)y0, wx = sx - (float)x0;
    const float* bp = in + (size_t)b * 8 * 16384;
    float v[8], m = -1e30f;
#pragma unroll
    for (int o = 0; o < 8; o++) {
        const float* p = bp + o * 16384;
        float a00 = p[y0*128+x0], a01 = p[y0*128+x1];
        float a10 = p[y1*128+x0], a11 = p[y1*128+x1];
        float t0 = a00 * (1.f - wy) + a10 * wy;
        float t1 = a01 * (1.f - wy) + a11 * wy;
        v[o] = t0 * (1.f - wx) + t1 * wx;
        m = fmaxf(m, v[o]);
    }
    float s = 0.f;
#pragma unroll
    for (int o = 0; o < 8; o++) { v[o] = expf(v[o] - m); s += v[o]; }
    float invs = 1.f / s;
    size_t base = ((size_t)b * 8) * 65536 + (size_t)y * 256 + x;
#pragma unroll
    for (int o = 0; o < 8; o++) out[base + (size_t)o * 65536] = v[o] * invs;
}

// ---------------------------------------------------------------------------
extern "C" void kernel_launch(void* const* d_in, const int* in_sizes, int n_in,
                              void* d_out, int out_size) {
    const float* x   = (const float*)d_in[0];
    const float* act = (const float*)d_in[1];
    const float* g[7]; const float* be[7];
    for (int i = 0; i < 7; i++) {
        g[i]  = (const float*)d_in[16 + 2*i];
        be[i] = (const float*)d_in[17 + 2*i];
    }
    float* out = (float*)d_out;
    float *pA = nullptr, *pB = nullptr;
    cudaGetSymbolAddress((void**)&pA, g_A);
    cudaGetSymbolAddress((void**)&pB, g_B);

    const int rows[7] = {3200, 6400, 12800, 25600, 51200, 102400, 512};
    const int offs[7] = {0, 3200, 9600, 22400, 48000, 99200, 201600};
    for (int i = 0; i < 7; i++) {
        gen_weights<<<(rows[i] + 255) / 256, 256>>>(
            (const float*)d_in[2 + 2*i], (const float*)d_in[3 + 2*i], act, rows[i], offs[i]);
    }

    bn_stats<<<NB * 8, 256>>>(x, g[0], be[0], 8, 65536);
    conv5x5<2, 1><<<dim3(8, 8, NB * 1), dim3(16, 16)>>>(x,  pA, 8,  256, offs[0], 1);
    bn_stats<<<NB * 16, 256>>>(pA, g[1], be[1], 16, 65536);
    conv5x5<1, 2><<<dim3(8, 8, NB * 1), dim3(16, 16)>>>(pA, pB, 16, 256, offs[1], 1);
    bn_stats<<<NB * 16, 256>>>(pB, g[2], be[2], 16, 65536);
    pool_bn<<<(NB * 16 * 16384 + 255) / 256, 256>>>(pB, pA);
    conv5x5<2, 0><<<dim3(4, 4, NB * 2), dim3(16, 16)>>>(pA, pB, 16, 128, offs[2], 2);
    bn_stats<<<NB * 32, 256>>>(pB, g[3], be[3], 32, 16384);
    conv5x5<1, 2><<<dim3(4, 4, NB * 2), dim3(16, 16)>>>(pB, pA, 32, 128, offs[3], 2);
    bn_stats<<<NB * 32, 256>>>(pA, g[4], be[4], 32, 16384);
    conv5x5<2, 1><<<dim3(4, 4, NB * 4), dim3(16, 16)>>>(pA, pB, 32, 128, offs[4], 4);
    bn_stats<<<NB * 64, 256>>>(pB, g[5], be[5], 64, 16384);
    conv5x5<1, 2><<<dim3(4, 4, NB * 4), dim3(16, 16)>>>(pB, pA, 64, 128, offs[5], 4);
    bn_stats<<<NB * 64, 256>>>(pA, g[6], be[6], 64, 16384);
    conv1x1<<<dim3(64, NB), 256>>>(pA, pB);
    up_softmax<<<(NB * 65536 + 255) / 256, 256>>>(pB, out);
}

// round 7
// speedup vs baseline: 1.1501x; 1.1501x over previous
#include <cuda_runtime.h>
#include <math.h>
#include <stdint.h>

#define NB 32
#define WTOT 202112
#define SAMP 864000

__device__ float g_y[NB * WTOT];
__device__ float g_A[NB * 1048576];
__device__ float g_B[NB * 1048576];
__device__ float g_stats[NB * 64 * 2];
__device__ unsigned char g_wimg[(size_t)NB * SAMP];  // per-sample bf16 hi/lo weight images

// ---------------- helpers ----------------
__device__ __forceinline__ uint16_t f2bf(float v) {
    uint16_t r; asm("cvt.rn.bf16.f32 %0, %1;" : "=h"(r) : "f"(v)); return r;
}
__device__ __forceinline__ unsigned long long pack2(float lo, float hi) {
    unsigned long long r; asm("mov.b64 %0, {%1, %2};" : "=l"(r) : "f"(lo), "f"(hi)); return r;
}
__device__ __forceinline__ void ffma2(unsigned long long& d, unsigned long long a, unsigned long long b) {
    asm("fma.rn.f32x2 %0, %1, %2, %0;" : "+l"(d) : "l"(a), "l"(b));
}
__device__ __forceinline__ void unpack2(unsigned long long v, float& lo, float& hi) {
    asm("mov.b64 {%0, %1}, %2;" : "=f"(lo), "=f"(hi) : "l"(v));
}
__device__ __forceinline__ void mma16816(float* c, uint32_t a0, uint32_t a1, uint32_t a2, uint32_t a3,
                                         uint32_t b0, uint32_t b1) {
    asm volatile("mma.sync.aligned.m16n8k16.row.col.f32.bf16.bf16.f32 "
        "{%0,%1,%2,%3}, {%4,%5,%6,%7}, {%8,%9}, {%0,%1,%2,%3};"
        : "+f"(c[0]), "+f"(c[1]), "+f"(c[2]), "+f"(c[3])
        : "r"(a0), "r"(a1), "r"(a2), "r"(a3), "r"(b0), "r"(b1));
}

// ---------------- weight generation ----------------
__global__ void gen_weights(const float* __restrict__ W, const float* __restrict__ bias,
                            const float* __restrict__ act, int rows, int off) {
    __shared__ float sa[NB * 32];
    for (int i = threadIdx.x; i < NB * 32; i += blockDim.x) sa[i] = act[i];
    __syncthreads();
    int r = blockIdx.x * blockDim.x + threadIdx.x;
    if (r >= rows) return;
    float w[32];
    const float4* wp = reinterpret_cast<const float4*>(W + (size_t)r * 32);
#pragma unroll
    for (int i = 0; i < 8; i++) { float4 v = wp[i]; w[4*i]=v.x; w[4*i+1]=v.y; w[4*i+2]=v.z; w[4*i+3]=v.w; }
    float bv = bias[r];
    for (int s = 0; s < NB; s++) {
        float acc = bv;
#pragma unroll
        for (int k = 0; k < 32; k++) acc = fmaf(w[k], sa[s*32+k], acc);
        g_y[(size_t)s * WTOT + off + r] = acc;
    }
}

// ---------------- weight image prep ----------------
// Image per (sample, layer): [chunk][ hi: [tap][cout][18ch] bf16 | lo: same ]
__global__ void prep_w(int wOff, int Cout, int Cin, int imgOff) {
    int b = blockIdx.y;
    int per = 25 * Cout * 18;
    int total = (Cin / 16) * per;
    int e = blockIdx.x * 256 + threadIdx.x;
    if (e >= total) return;
    int chunk = e / per; int rem = e - chunk * per;
    int tap = rem / (Cout * 18); int rem2 = rem - tap * Cout * 18;
    int cout = rem2 / 18; int cc = rem2 - cout * 18;
    float v = 0.f;
    if (cc < 16)
        v = g_y[(size_t)b * WTOT + wOff + ((size_t)cout * Cin + chunk * 16 + cc) * 25 + tap];
    uint16_t hb = f2bf(v);
    uint16_t lb = f2bf(v - __uint_as_float((uint32_t)hb << 16));
    int WBl = 25 * Cout * 36;
    size_t base = (size_t)b * SAMP + imgOff + (size_t)chunk * 2 * WBl
                + ((size_t)(tap * Cout + cout) * 18 + cc) * 2;
    *(uint16_t*)(g_wimg + base) = hb;
    *(uint16_t*)(g_wimg + base + WBl) = lb;
}

// ---------------- BN stats ----------------
__global__ void bn_stats(const float* __restrict__ src, const float* __restrict__ g,
                         const float* __restrict__ be, int C, int HW) {
    int plane = blockIdx.x;
    int c = plane % C;
    const float* p = src + (size_t)plane * HW;
    float s = 0.f, s2 = 0.f;
    for (int i = threadIdx.x; i < HW; i += 256) { float v = p[i]; s += v; s2 = fmaf(v, v, s2); }
    __shared__ float sh0[256], sh1[256];
    sh0[threadIdx.x] = s; sh1[threadIdx.x] = s2;
    __syncthreads();
    for (int ofs = 128; ofs > 0; ofs >>= 1) {
        if (threadIdx.x < ofs) { sh0[threadIdx.x] += sh0[threadIdx.x+ofs]; sh1[threadIdx.x] += sh1[threadIdx.x+ofs]; }
        __syncthreads();
    }
    if (threadIdx.x == 0) {
        float inv = 1.f / (float)HW;
        float m = sh0[0] * inv;
        float var = sh1[0] * inv - m * m;
        float sc = g[c] * rsqrtf(var + 1e-5f);
        g_stats[plane*2] = sc;
        g_stats[plane*2+1] = be[c] - m * sc;
    }
}

// ---------------- scalar conv (convs 1-2, S=256) ----------------
template<int DIL, int MODE>
__global__ __launch_bounds__(256)
void conv5x5(const float* __restrict__ in, float* __restrict__ out,
             int Cin, int S, int wOff, int grps) {
    constexpr int PAD = 2 * DIL;
    constexpr int TIN = 32 + 4 * DIL;
    constexpr int RS  = 48;
    __shared__ float sm[TIN * RS];
    __shared__ __align__(8) float sw[25 * 16];
    int z = blockIdx.z;
    int b = z / grps, gq = z - b * grps;
    int gbase = gq * 16;
    int x0 = blockIdx.x * 32, y0 = blockIdx.y * 32;
    int tx = threadIdx.x, ty = threadIdx.y;
    int tid = ty * 16 + tx;
    unsigned long long acc[4][8];
#pragma unroll
    for (int p = 0; p < 4; p++)
#pragma unroll
        for (int j = 0; j < 8; j++) acc[p][j] = 0ULL;
    const float* wb = g_y + (size_t)b * WTOT + wOff;
    for (int c = 0; c < Cin; c++) {
        float sc = 1.f, sf = 0.f;
        if (MODE) { sc = g_stats[(b*Cin+c)*2]; sf = g_stats[(b*Cin+c)*2+1]; }
        const float* ip = in + ((size_t)(b * Cin + c)) * S * S;
        for (int i = tid; i < TIN * TIN; i += 256) {
            int r = i / TIN, col = i - r * TIN;
            int iy = y0 - PAD + r, ix = x0 - PAD + col;
            float v = 0.f;
            if (iy >= 0 && iy < S && ix >= 0 && ix < S) {
                v = ip[(size_t)iy * S + ix];
                if (MODE) { v = fmaf(v, sc, sf); if (MODE == 2) v = fmaxf(v, 0.f); }
            }
            sm[r * RS + col] = v;
        }
        for (int i = tid; i < 400; i += 256) {
            int k = i >> 4, gg = i & 15;
            sw[i] = wb[((size_t)(gbase + gg) * Cin + c) * 25 + k];
        }
        __syncthreads();
#pragma unroll 1
        for (int ky = 0; ky < 5; ky++) {
#pragma unroll
            for (int kx = 0; kx < 5; kx++) {
                int base = (ty + ky * DIL) * RS + tx + kx * DIL;
                unsigned long long T0 = pack2(sm[base], sm[base]);
                unsigned long long T1 = pack2(sm[base+16], sm[base+16]);
                unsigned long long T2 = pack2(sm[base+16*RS], sm[base+16*RS]);
                unsigned long long T3 = pack2(sm[base+16*RS+16], sm[base+16*RS+16]);
                const unsigned long long* wq = reinterpret_cast<const unsigned long long*>(sw + (ky*5+kx)*16);
#pragma unroll
                for (int j = 0; j < 8; j++) {
                    unsigned long long w2 = wq[j];
                    ffma2(acc[0][j], T0, w2); ffma2(acc[1][j], T1, w2);
                    ffma2(acc[2][j], T2, w2); ffma2(acc[3][j], T3, w2);
                }
            }
        }
        __syncthreads();
    }
    int Cout = grps * 16;
#pragma unroll
    for (int j = 0; j < 8; j++) {
        float e0, e1;
        float* op0 = out + ((size_t)(b * Cout + gbase + 2*j)) * S * S;
        float* op1 = op0 + (size_t)S * S;
        size_t o00 = (size_t)(y0 + ty) * S + x0 + tx;
        size_t o10 = (size_t)(y0 + ty + 16) * S + x0 + tx;
        unpack2(acc[0][j], e0, e1); op0[o00] = e0; op1[o00] = e1;
        unpack2(acc[1][j], e0, e1); op0[o00+16] = e0; op1[o00+16] = e1;
        unpack2(acc[2][j], e0, e1); op0[o10] = e0; op1[o10] = e1;
        unpack2(acc[3][j], e0, e1); op0[o10+16] = e0; op1[o10+16] = e1;
    }
}

// ---------------- mma.sync conv (convs 3-6, S=128) -------------------------
// CTA = (b, one output row y), 256 threads = 8 warps x 16 pixels.
// Implicit GEMM: M=16 px (per warp), N=COUT, K=16 ch per chunk x 25 taps.
// Split-bf16 3-pass: D += Ah*Bh + Al*Bh + Ah*Bl.
// smem: [wHi|wLo] (pre-swizzled copy) + stage [5][136][20ch] bf16 hi/lo.
template<int DIL, int MODE, int CIN, int COUT>
__global__ __launch_bounds__(256)
void conv_mma(const float* __restrict__ in, float* __restrict__ out, int imgOff) {
    constexpr int WB = 25 * COUT * 36;        // bytes per hi (or lo) weight block
    constexpr int NC = CIN / 16;
    extern __shared__ __align__(16) char dsm[];
    uint16_t* sHi = (uint16_t*)(dsm + 2 * WB);     // [5][136][20]
    const int tid = threadIdx.x, w = tid >> 5, lane = tid & 31;
    const int g = lane >> 2, t = lane & 3;
    const int b = blockIdx.y, y = blockIdx.x;
    float acc[COUT / 8][4];
#pragma unroll
    for (int n = 0; n < COUT / 8; n++)
#pragma unroll
        for (int j = 0; j < 4; j++) acc[n][j] = 0.f;
    const unsigned char* img = g_wimg + (size_t)b * SAMP + imgOff;
    const int x0 = w * 16;

#pragma unroll 1
    for (int chunk = 0; chunk < NC; chunk++) {
        __syncthreads();
        // copy weights (contiguous, pre-formatted)
        {
            const uint4* src = (const uint4*)(img + (size_t)chunk * 2 * WB);
            uint4* dst = (uint4*)dsm;
            for (int i = tid; i < 2 * WB / 16; i += 256) dst[i] = src[i];
        }
        // stage input rows y+(r-2)*DIL, bf16 hi/lo with BN folded
        {
            int cb = chunk * 16;
            for (int idx = tid; idx < 16 * 680; idx += 256) {
                int ch = idx / 680; int rem = idx - ch * 680;
                int r = rem / 136; int xp = rem - r * 136;
                int iy = y + (r - 2) * DIL, ix = xp - 2 * DIL;
                float v = 0.f;
                if (iy >= 0 && iy < 128 && ix >= 0 && ix < 128) {
                    int c = cb + ch;
                    v = in[((size_t)(b * CIN + c)) * 16384 + iy * 128 + ix];
                    if (MODE) {
                        v = fmaf(v, g_stats[(b*CIN+c)*2], g_stats[(b*CIN+c)*2+1]);
                        if (MODE == 2) v = fmaxf(v, 0.f);
                    }
                }
                uint16_t hb = f2bf(v);
                float lo = v - __uint_as_float((uint32_t)hb << 16);
                int o = (r * 136 + xp) * 20 + ch;
                sHi[o] = hb;
                sHi[o + 13600] = f2bf(lo);
            }
        }
        __syncthreads();
#pragma unroll 1
        for (int ky = 0; ky < 5; ky++) {
#pragma unroll 1
            for (int kx = 0; kx < 5; kx++) {
                const char* aB = (const char*)(sHi + ((ky * 136) + x0 + kx * DIL) * 20) + g * 40 + t * 4;
                uint32_t ah0 = *(const uint32_t*)(aB);
                uint32_t ah1 = *(const uint32_t*)(aB + 320);
                uint32_t ah2 = *(const uint32_t*)(aB + 16);
                uint32_t ah3 = *(const uint32_t*)(aB + 336);
                uint32_t al0 = *(const uint32_t*)(aB + 27200);
                uint32_t al1 = *(const uint32_t*)(aB + 27520);
                uint32_t al2 = *(const uint32_t*)(aB + 27216);
                uint32_t al3 = *(const uint32_t*)(aB + 27536);
                const char* wB = dsm + ((ky * 5 + kx) * COUT + g) * 36 + t * 4;
#pragma unroll
                for (int n = 0; n < COUT / 8; n++) {
                    const char* wp = wB + n * 288;
                    uint32_t bh0 = *(const uint32_t*)(wp);
                    uint32_t bh1 = *(const uint32_t*)(wp + 16);
                    uint32_t bl0 = *(const uint32_t*)(wp + WB);
                    uint32_t bl1 = *(const uint32_t*)(wp + WB + 16);
                    mma16816(acc[n], ah0, ah1, ah2, ah3, bh0, bh1);
                    mma16816(acc[n], al0, al1, al2, al3, bh0, bh1);
                    mma16816(acc[n], ah0, ah1, ah2, ah3, bl0, bl1);
                }
            }
        }
    }
    // store: c0=(px x0+g, oc n8+2t), c1=(+oc1), c2=(px+8), c3=(px+8,+oc1)
    int px = x0 + g;
    float* orow = out + ((size_t)b * COUT) * 16384 + (size_t)y * 128;
#pragma unroll
    for (int n = 0; n < COUT / 8; n++) {
        float* p0 = orow + ((size_t)(n * 8 + 2 * t)) * 16384;
        float* p1 = p0 + 16384;
        p0[px]     = acc[n][0];
        p1[px]     = acc[n][1];
        p0[px + 8] = acc[n][2];
        p1[px + 8] = acc[n][3];
    }
}

// ---------------- pool / 1x1 / upsample+softmax ----------------
__global__ void pool_bn(const float* __restrict__ in, float* __restrict__ out) {
    int idx = blockIdx.x * blockDim.x + threadIdx.x;
    if (idx >= NB * 16 * 128 * 128) return;
    int x = idx & 127, y = (idx >> 7) & 127, pc = idx >> 14;
    const float* ip = in + (size_t)pc * 65536;
    int o2 = (2 * y) * 256 + 2 * x;
    float v = (ip[o2] + ip[o2+1] + ip[o2+256] + ip[o2+257]) * 0.25f;
    out[idx] = fmaf(v, g_stats[pc*2], g_stats[pc*2+1]);
}

__global__ void conv1x1(const float* __restrict__ in, float* __restrict__ out) {
    __shared__ float sw[512];
    int b = blockIdx.y;
    const float* wb = g_y + (size_t)b * WTOT + 201600;
    for (int i = threadIdx.x; i < 512; i += blockDim.x) sw[i] = wb[i];
    __syncthreads();
    int pix = blockIdx.x * blockDim.x + threadIdx.x;
    if (pix >= 16384) return;
    float acc[8] = {0,0,0,0,0,0,0,0};
    for (int c = 0; c < 64; c++) {
        float v = in[((size_t)(b*64 + c)) * 16384 + pix];
        v = fmaf(v, g_stats[(b*64+c)*2], g_stats[(b*64+c)*2+1]);
#pragma unroll
        for (int o = 0; o < 8; o++) acc[o] = fmaf(v, sw[o*64 + c], acc[o]);
    }
#pragma unroll
    for (int o = 0; o < 8; o++) out[((size_t)(b*8 + o)) * 16384 + pix] = acc[o];
}

__global__ void up_softmax(const float* __restrict__ in, float* __restrict__ out) {
    int idx = blockIdx.x * blockDim.x + threadIdx.x;
    if (idx >= NB * 65536) return;
    int x = idx & 255, y = (idx >> 8) & 255, b = idx >> 16;
    const float r = 127.0f / 255.0f;
    float sy = y * r, sx = x * r;
    int y0 = (int)sy, x0 = (int)sx;
    int y1 = min(y0 + 1, 127), x1 = min(x0 + 1, 127);
    float wy = sy - (float)y0, wx = sx - (float)x0;
    const float* bp = in + (size_t)b * 8 * 16384;
    float v[8], m = -1e30f;
#pragma unroll
    for (int o = 0; o < 8; o++) {
        const float* p = bp + o * 16384;
        float a00 = p[y0*128+x0], a01 = p[y0*128+x1];
        float a10 = p[y1*128+x0], a11 = p[y1*128+x1];
        float t0 = a00 * (1.f - wy) + a10 * wy;
        float t1 = a01 * (1.f - wy) + a11 * wy;
        v[o] = t0 * (1.f - wx) + t1 * wx;
        m = fmaxf(m, v[o]);
    }
    float s = 0.f;
#pragma unroll
    for (int o = 0; o < 8; o++) { v[o] = expf(v[o] - m); s += v[o]; }
    float invs = 1.f / s;
    size_t base = ((size_t)b * 8) * 65536 + (size_t)y * 256 + x;
#pragma unroll
    for (int o = 0; o < 8; o++) out[base + (size_t)o * 65536] = v[o] * invs;
}

// ---------------------------------------------------------------------------
extern "C" void kernel_launch(void* const* d_in, const int* in_sizes, int n_in,
                              void* d_out, int out_size) {
    const float* x   = (const float*)d_in[0];
    const float* act = (const float*)d_in[1];
    const float* g[7]; const float* be[7];
    for (int i = 0; i < 7; i++) { g[i] = (const float*)d_in[16 + 2*i]; be[i] = (const float*)d_in[17 + 2*i]; }
    float* out = (float*)d_out;
    float *pA = nullptr, *pB = nullptr;
    cudaGetSymbolAddress((void**)&pA, g_A);
    cudaGetSymbolAddress((void**)&pB, g_B);

    // smem sizes: 2*WB + 54400 stage
    const int SM3 = 2*25*32*36 + 54400;   // 112000
    const int SM4 = SM3;
    const int SM5 = 2*25*64*36 + 54400;   // 169600
    const int SM6 = SM5;
    cudaFuncSetAttribute(conv_mma<2,0,16,32>, cudaFuncAttributeMaxDynamicSharedMemorySize, SM3);
    cudaFuncSetAttribute(conv_mma<1,2,32,32>, cudaFuncAttributeMaxDynamicSharedMemorySize, SM4);
    cudaFuncSetAttribute(conv_mma<2,1,32,64>, cudaFuncAttributeMaxDynamicSharedMemorySize, SM5);
    cudaFuncSetAttribute(conv_mma<1,2,64,64>, cudaFuncAttributeMaxDynamicSharedMemorySize, SM6);

    const int rows[7] = {3200, 6400, 12800, 25600, 51200, 102400, 512};
    const int offs[7] = {0, 3200, 9600, 22400, 48000, 99200, 201600};
    for (int i = 0; i < 7; i++) {
        gen_weights<<<(rows[i] + 255) / 256, 256>>>(
            (const float*)d_in[2 + 2*i], (const float*)d_in[3 + 2*i], act, rows[i], offs[i]);
    }
    // weight images (layers 3-6): wOff, Cout, Cin, imgOff
    prep_w<<<dim3(57,  NB), 256>>>(offs[2], 32, 16, 0);        // 14400 el
    prep_w<<<dim3(113, NB), 256>>>(offs[3], 32, 32, 57600);    // 28800
    prep_w<<<dim3(225, NB), 256>>>(offs[4], 64, 32, 172800);   // 57600
    prep_w<<<dim3(450, NB), 256>>>(offs[5], 64, 64, 403200);   // 115200

    bn_stats<<<NB * 8, 256>>>(x, g[0], be[0], 8, 65536);
    conv5x5<2, 1><<<dim3(8, 8, NB), dim3(16, 16)>>>(x,  pA, 8,  256, offs[0], 1);
    bn_stats<<<NB * 16, 256>>>(pA, g[1], be[1], 16, 65536);
    conv5x5<1, 2><<<dim3(8, 8, NB), dim3(16, 16)>>>(pA, pB, 16, 256, offs[1], 1);
    bn_stats<<<NB * 16, 256>>>(pB, g[2], be[2], 16, 65536);
    pool_bn<<<(NB * 16 * 16384 + 255) / 256, 256>>>(pB, pA);

    conv_mma<2,0,16,32><<<dim3(128, NB), 256, SM3>>>(pA, pB, 0);
    bn_stats<<<NB * 32, 256>>>(pB, g[3], be[3], 32, 16384);
    conv_mma<1,2,32,32><<<dim3(128, NB), 256, SM4>>>(pB, pA, 57600);
    bn_stats<<<NB * 32, 256>>>(pA, g[4], be[4], 32, 16384);
    conv_mma<2,1,32,64><<<dim3(128, NB), 256, SM5>>>(pA, pB, 172800);
    bn_stats<<<NB * 64, 256>>>(pB, g[5], be[5], 64, 16384);
    conv_mma<1,2,64,64><<<dim3(128, NB), 256, SM6>>>(pB, pA, 403200);
    bn_stats<<<NB * 64, 256>>>(pA, g[6], be[6], 64, 16384);

    conv1x1<<<dim3(64, NB), 256>>>(pA, pB);
    up_softmax<<<(NB * 65536 + 255) / 256, 256>>>(pB, out);
}

// round 8
// speedup vs baseline: 1.8088x; 1.5727x over previous
#include <cuda_runtime.h>
#include <math.h>
#include <stdint.h>

#define NB 32
#define WTOT 202112
#define SAMP 892800

__device__ float g_y[NB * WTOT];
__device__ float g_A[NB * 1048576];
__device__ float g_B[NB * 1048576];
__device__ float g_stats[NB * 64 * 2];
__device__ unsigned char g_wimg[(size_t)NB * SAMP];  // per-sample bf16 hi/lo weight images

// ---------------- helpers ----------------
__device__ __forceinline__ uint16_t f2bf(float v) {
    uint16_t r; asm("cvt.rn.bf16.f32 %0, %1;" : "=h"(r) : "f"(v)); return r;
}
__device__ __forceinline__ uint32_t cvt2bf(float hi, float lo) {   // {hi | lo}
    uint32_t r; asm("cvt.rn.bf16x2.f32 %0, %1, %2;" : "=r"(r) : "f"(hi), "f"(lo)); return r;
}
__device__ __forceinline__ unsigned long long pack2(float lo, float hi) {
    unsigned long long r; asm("mov.b64 %0, {%1, %2};" : "=l"(r) : "f"(lo), "f"(hi)); return r;
}
__device__ __forceinline__ void ffma2(unsigned long long& d, unsigned long long a, unsigned long long b) {
    asm("fma.rn.f32x2 %0, %1, %2, %0;" : "+l"(d) : "l"(a), "l"(b));
}
__device__ __forceinline__ void unpack2(unsigned long long v, float& lo, float& hi) {
    asm("mov.b64 {%0, %1}, %2;" : "=f"(lo), "=f"(hi) : "l"(v));
}
__device__ __forceinline__ void mma16816(float* c, uint32_t a0, uint32_t a1, uint32_t a2, uint32_t a3,
                                         uint32_t b0, uint32_t b1) {
    asm volatile("mma.sync.aligned.m16n8k16.row.col.f32.bf16.bf16.f32 "
        "{%0,%1,%2,%3}, {%4,%5,%6,%7}, {%8,%9}, {%0,%1,%2,%3};"
        : "+f"(c[0]), "+f"(c[1]), "+f"(c[2]), "+f"(c[3])
        : "r"(a0), "r"(a1), "r"(a2), "r"(a3), "r"(b0), "r"(b1));
}

// ---------------- weight generation ----------------
__global__ void gen_weights(const float* __restrict__ W, const float* __restrict__ bias,
                            const float* __restrict__ act, int rows, int off) {
    __shared__ float sa[NB * 32];
    for (int i = threadIdx.x; i < NB * 32; i += blockDim.x) sa[i] = act[i];
    __syncthreads();
    int r = blockIdx.x * blockDim.x + threadIdx.x;
    if (r >= rows) return;
    float w[32];
    const float4* wp = reinterpret_cast<const float4*>(W + (size_t)r * 32);
#pragma unroll
    for (int i = 0; i < 8; i++) { float4 v = wp[i]; w[4*i]=v.x; w[4*i+1]=v.y; w[4*i+2]=v.z; w[4*i+3]=v.w; }
    float bv = bias[r];
    for (int s = 0; s < NB; s++) {
        float acc = bv;
#pragma unroll
        for (int k = 0; k < 32; k++) acc = fmaf(w[k], sa[s*32+k], acc);
        g_y[(size_t)s * WTOT + off + r] = acc;
    }
}

// ---------------- weight image prep ----------------
// Image per (sample, layer): [chunk][ hi: [tap][cout][18ch] bf16 | lo: same ]
__global__ void prep_w(int wOff, int Cout, int Cin, int imgOff) {
    int b = blockIdx.y;
    int per = 25 * Cout * 18;
    int total = (Cin / 16) * per;
    int e = blockIdx.x * 256 + threadIdx.x;
    if (e >= total) return;
    int chunk = e / per; int rem = e - chunk * per;
    int tap = rem / (Cout * 18); int rem2 = rem - tap * Cout * 18;
    int cout = rem2 / 18; int cc = rem2 - cout * 18;
    float v = 0.f;
    if (cc < 16)
        v = g_y[(size_t)b * WTOT + wOff + ((size_t)cout * Cin + chunk * 16 + cc) * 25 + tap];
    uint16_t hb = f2bf(v);
    uint16_t lb = f2bf(v - __uint_as_float((uint32_t)hb << 16));
    int WBl = 25 * Cout * 36;
    size_t base = (size_t)b * SAMP + imgOff + (size_t)chunk * 2 * WBl
                + ((size_t)(tap * Cout + cout) * 18 + cc) * 2;
    *(uint16_t*)(g_wimg + base) = hb;
    *(uint16_t*)(g_wimg + base + WBl) = lb;
}

// ---------------- BN stats ----------------
__global__ void bn_stats(const float* __restrict__ src, const float* __restrict__ g,
                         const float* __restrict__ be, int C, int HW) {
    int plane = blockIdx.x;
    int c = plane % C;
    const float* p = src + (size_t)plane * HW;
    float s = 0.f, s2 = 0.f;
    for (int i = threadIdx.x; i < HW; i += 256) { float v = p[i]; s += v; s2 = fmaf(v, v, s2); }
    __shared__ float sh0[256], sh1[256];
    sh0[threadIdx.x] = s; sh1[threadIdx.x] = s2;
    __syncthreads();
    for (int ofs = 128; ofs > 0; ofs >>= 1) {
        if (threadIdx.x < ofs) { sh0[threadIdx.x] += sh0[threadIdx.x+ofs]; sh1[threadIdx.x] += sh1[threadIdx.x+ofs]; }
        __syncthreads();
    }
    if (threadIdx.x == 0) {
        float inv = 1.f / (float)HW;
        float m = sh0[0] * inv;
        float var = sh1[0] * inv - m * m;
        float sc = g[c] * rsqrtf(var + 1e-5f);
        g_stats[plane*2] = sc;
        g_stats[plane*2+1] = be[c] - m * sc;
    }
}

// ---------------- scalar conv (conv1 only, S=256, Cin=8) ----------------
template<int DIL, int MODE>
__global__ __launch_bounds__(256)
void conv5x5(const float* __restrict__ in, float* __restrict__ out,
             int Cin, int S, int wOff, int grps) {
    constexpr int PAD = 2 * DIL;
    constexpr int TIN = 32 + 4 * DIL;
    constexpr int RS  = 48;
    __shared__ float sm[TIN * RS];
    __shared__ __align__(8) float sw[25 * 16];
    int z = blockIdx.z;
    int b = z / grps, gq = z - b * grps;
    int gbase = gq * 16;
    int x0 = blockIdx.x * 32, y0 = blockIdx.y * 32;
    int tx = threadIdx.x, ty = threadIdx.y;
    int tid = ty * 16 + tx;
    unsigned long long acc[4][8];
#pragma unroll
    for (int p = 0; p < 4; p++)
#pragma unroll
        for (int j = 0; j < 8; j++) acc[p][j] = 0ULL;
    const float* wb = g_y + (size_t)b * WTOT + wOff;
    for (int c = 0; c < Cin; c++) {
        float sc = 1.f, sf = 0.f;
        if (MODE) { sc = g_stats[(b*Cin+c)*2]; sf = g_stats[(b*Cin+c)*2+1]; }
        const float* ip = in + ((size_t)(b * Cin + c)) * S * S;
        for (int i = tid; i < TIN * TIN; i += 256) {
            int r = i / TIN, col = i - r * TIN;
            int iy = y0 - PAD + r, ix = x0 - PAD + col;
            float v = 0.f;
            if (iy >= 0 && iy < S && ix >= 0 && ix < S) {
                v = ip[(size_t)iy * S + ix];
                if (MODE) { v = fmaf(v, sc, sf); if (MODE == 2) v = fmaxf(v, 0.f); }
            }
            sm[r * RS + col] = v;
        }
        for (int i = tid; i < 400; i += 256) {
            int k = i >> 4, gg = i & 15;
            sw[i] = wb[((size_t)(gbase + gg) * Cin + c) * 25 + k];
        }
        __syncthreads();
#pragma unroll 1
        for (int ky = 0; ky < 5; ky++) {
#pragma unroll
            for (int kx = 0; kx < 5; kx++) {
                int base = (ty + ky * DIL) * RS + tx + kx * DIL;
                unsigned long long T0 = pack2(sm[base], sm[base]);
                unsigned long long T1 = pack2(sm[base+16], sm[base+16]);
                unsigned long long T2 = pack2(sm[base+16*RS], sm[base+16*RS]);
                unsigned long long T3 = pack2(sm[base+16*RS+16], sm[base+16*RS+16]);
                const unsigned long long* wq = reinterpret_cast<const unsigned long long*>(sw + (ky*5+kx)*16);
#pragma unroll
                for (int j = 0; j < 8; j++) {
                    unsigned long long w2 = wq[j];
                    ffma2(acc[0][j], T0, w2); ffma2(acc[1][j], T1, w2);
                    ffma2(acc[2][j], T2, w2); ffma2(acc[3][j], T3, w2);
                }
            }
        }
        __syncthreads();
    }
    int Cout = grps * 16;
#pragma unroll
    for (int j = 0; j < 8; j++) {
        float e0, e1;
        float* op0 = out + ((size_t)(b * Cout + gbase + 2*j)) * S * S;
        float* op1 = op0 + (size_t)S * S;
        size_t o00 = (size_t)(y0 + ty) * S + x0 + tx;
        size_t o10 = (size_t)(y0 + ty + 16) * S + x0 + tx;
        unpack2(acc[0][j], e0, e1); op0[o00] = e0; op1[o00] = e1;
        unpack2(acc[1][j], e0, e1); op0[o00+16] = e0; op1[o00+16] = e1;
        unpack2(acc[2][j], e0, e1); op0[o10] = e0; op1[o10] = e1;
        unpack2(acc[3][j], e0, e1); op0[o10+16] = e0; op1[o10+16] = e1;
    }
}

// ---------------- mma.sync conv (convs 2-6) ---------------------------------
// CTA = (b, 4 output rows). 8 warps: warp w -> row y0+(w>>1), x-half (w&1)*(S/2),
// T = S/32 m16 tiles per warp. Split-bf16 3-pass: D += Ah*Bh + Al*Bh + Ah*Bl.
// Stage layout: u32 pairs [16][PSTRIDE], PSTRIDE % 32 == 8 -> conflict-free A LDS.
template<int DIL, int MODE, int CIN, int COUT, int S>
__global__ __launch_bounds__(256, 1)
void conv_mma(const float* __restrict__ in, float* __restrict__ out, int imgOff) {
    constexpr int WB = 25 * COUT * 36;
    constexpr int NC = CIN / 16;
    constexpr int XP = S + 4 * DIL;
    constexpr int R  = 4 + 4 * DIL;
    constexpr int PS0 = R * XP;
    constexpr int PSTRIDE = PS0 + ((40 - (PS0 & 31)) & 31);
    constexpr int T  = S / 32;
    constexpr int NN = COUT / 8;
    extern __shared__ __align__(16) char dsm[];
    uint32_t* sStage = (uint32_t*)(dsm + 2 * WB);
    const int tid = threadIdx.x, w = tid >> 5, lane = tid & 31;
    const int g = lane >> 2, t = lane & 3;
    const int b = blockIdx.y, y0 = blockIdx.x * 4;
    const int ry = w >> 1, xseg = (w & 1) * (S / 2);
    float acc[T][NN][4];
#pragma unroll
    for (int i = 0; i < T; i++)
#pragma unroll
        for (int n = 0; n < NN; n++)
#pragma unroll
            for (int j = 0; j < 4; j++) acc[i][n][j] = 0.f;
    const unsigned char* img = g_wimg + (size_t)b * SAMP + imgOff;

#pragma unroll 1
    for (int chunk = 0; chunk < NC; chunk++) {
        __syncthreads();
        {   // copy pre-formatted weights (hi|lo)
            const uint4* src = (const uint4*)(img + (size_t)chunk * 2 * WB);
            uint4* dst = (uint4*)dsm;
            for (int i = tid; i < 2 * WB / 16; i += 256) dst[i] = src[i];
        }
        {   // stage 16 channels as bf16x2 pairs (hi p0-7, lo p8-15), BN folded
            int cb = chunk * 16;
            for (int idx = tid; idx < 8 * PS0; idx += 256) {
                int p = idx / PS0, rem = idx - p * PS0;
                int r = rem / XP, xp = rem - r * XP;
                int iy = y0 + r - 2 * DIL, ix = xp - 2 * DIL;
                float v0 = 0.f, v1 = 0.f;
                if (iy >= 0 && iy < S && ix >= 0 && ix < S) {
                    int c0 = cb + p * 2;
                    const float* bp = in + ((size_t)(b * CIN + c0)) * (S * S) + (size_t)iy * S + ix;
                    v0 = bp[0]; v1 = bp[(size_t)S * S];
                    if (MODE) {
                        v0 = fmaf(v0, g_stats[(b*CIN+c0)*2],   g_stats[(b*CIN+c0)*2+1]);
                        v1 = fmaf(v1, g_stats[(b*CIN+c0+1)*2], g_stats[(b*CIN+c0+1)*2+1]);
                        if (MODE == 2) { v0 = fmaxf(v0, 0.f); v1 = fmaxf(v1, 0.f); }
                    }
                }
                uint32_t hp = cvt2bf(v1, v0);
                float e0 = v0 - __uint_as_float(hp << 16);
                float e1 = v1 - __uint_as_float(hp & 0xffff0000u);
                uint32_t lp = cvt2bf(e1, e0);
                sStage[p * PSTRIDE + rem]       = hp;
                sStage[(8 + p) * PSTRIDE + rem] = lp;
            }
        }
        __syncthreads();
#pragma unroll 1
        for (int ky = 0; ky < 5; ky++) {
#pragma unroll 1
            for (int kx = 0; kx < 5; kx++) {
                int off = (ry + ky * DIL) * XP + xseg + kx * DIL + g;
                uint32_t ah[T][4], al[T][4];
#pragma unroll
                for (int i = 0; i < T; i++) {
                    int o = off + i * 16;
                    ah[i][0] = sStage[t * PSTRIDE + o];
                    ah[i][1] = sStage[t * PSTRIDE + o + 8];
                    ah[i][2] = sStage[(t + 4) * PSTRIDE + o];
                    ah[i][3] = sStage[(t + 4) * PSTRIDE + o + 8];
                    al[i][0] = sStage[(t + 8) * PSTRIDE + o];
                    al[i][1] = sStage[(t + 8) * PSTRIDE + o + 8];
                    al[i][2] = sStage[(t + 12) * PSTRIDE + o];
                    al[i][3] = sStage[(t + 12) * PSTRIDE + o + 8];
                }
                const char* wB = dsm + ((ky * 5 + kx) * COUT + g) * 36 + t * 4;
#pragma unroll
                for (int n = 0; n < NN; n++) {
                    const char* wp = wB + n * 288;
                    uint32_t bh0 = *(const uint32_t*)(wp);
                    uint32_t bh1 = *(const uint32_t*)(wp + 16);
                    uint32_t bl0 = *(const uint32_t*)(wp + WB);
                    uint32_t bl1 = *(const uint32_t*)(wp + WB + 16);
#pragma unroll
                    for (int i = 0; i < T; i++) {
                        mma16816(acc[i][n], ah[i][0], ah[i][1], ah[i][2], ah[i][3], bh0, bh1);
                        mma16816(acc[i][n], al[i][0], al[i][1], al[i][2], al[i][3], bh0, bh1);
                        mma16816(acc[i][n], ah[i][0], ah[i][1], ah[i][2], ah[i][3], bl0, bl1);
                    }
                }
            }
        }
    }
    int row = y0 + ry;
    float* orow = out + ((size_t)b * COUT) * (S * S) + (size_t)row * S;
#pragma unroll
    for (int i = 0; i < T; i++) {
        int px = xseg + i * 16 + g;
#pragma unroll
        for (int n = 0; n < NN; n++) {
            float* p0 = orow + ((size_t)(n * 8 + 2 * t)) * (S * S);
            float* p1 = p0 + (size_t)S * S;
            p0[px]     = acc[i][n][0];
            p1[px]     = acc[i][n][1];
            p0[px + 8] = acc[i][n][2];
            p1[px + 8] = acc[i][n][3];
        }
    }
}

// ---------------- pool / 1x1 / upsample+softmax ----------------
__global__ void pool_bn(const float* __restrict__ in, float* __restrict__ out) {
    int idx = blockIdx.x * blockDim.x + threadIdx.x;
    if (idx >= NB * 16 * 128 * 128) return;
    int x = idx & 127, y = (idx >> 7) & 127, pc = idx >> 14;
    const float* ip = in + (size_t)pc * 65536;
    int o2 = (2 * y) * 256 + 2 * x;
    float v = (ip[o2] + ip[o2+1] + ip[o2+256] + ip[o2+257]) * 0.25f;
    out[idx] = fmaf(v, g_stats[pc*2], g_stats[pc*2+1]);
}

__global__ void conv1x1(const float* __restrict__ in, float* __restrict__ out) {
    __shared__ float sw[512];
    int b = blockIdx.y;
    const float* wb = g_y + (size_t)b * WTOT + 201600;
    for (int i = threadIdx.x; i < 512; i += blockDim.x) sw[i] = wb[i];
    __syncthreads();
    int pix = blockIdx.x * blockDim.x + threadIdx.x;
    if (pix >= 16384) return;
    float acc[8] = {0,0,0,0,0,0,0,0};
    for (int c = 0; c < 64; c++) {
        float v = in[((size_t)(b*64 + c)) * 16384 + pix];
        v = fmaf(v, g_stats[(b*64+c)*2], g_stats[(b*64+c)*2+1]);
#pragma unroll
        for (int o = 0; o < 8; o++) acc[o] = fmaf(v, sw[o*64 + c], acc[o]);
    }
#pragma unroll
    for (int o = 0; o < 8; o++) out[((size_t)(b*8 + o)) * 16384 + pix] = acc[o];
}

__global__ void up_softmax(const float* __restrict__ in, float* __restrict__ out) {
    int idx = blockIdx.x * blockDim.x + threadIdx.x;
    if (idx >= NB * 65536) return;
    int x = idx & 255, y = (idx >> 8) & 255, b = idx >> 16;
    const float r = 127.0f / 255.0f;
    float sy = y * r, sx = x * r;
    int y0 = (int)sy, x0 = (int)sx;
    int y1 = min(y0 + 1, 127), x1 = min(x0 + 1, 127);
    float wy = sy - (float)y0, wx = sx - (float)x0;
    const float* bp = in + (size_t)b * 8 * 16384;
    float v[8], m = -1e30f;
#pragma unroll
    for (int o = 0; o < 8; o++) {
        const float* p = bp + o * 16384;
        float a00 = p[y0*128+x0], a01 = p[y0*128+x1];
        float a10 = p[y1*128+x0], a11 = p[y1*128+x1];
        float t0 = a00 * (1.f - wy) + a10 * wy;
        float t1 = a01 * (1.f - wy) + a11 * wy;
        v[o] = t0 * (1.f - wx) + t1 * wx;
        m = fmaxf(m, v[o]);
    }
    float s = 0.f;
#pragma unroll
    for (int o = 0; o < 8; o++) { v[o] = expf(v[o] - m); s += v[o]; }
    float invs = 1.f / s;
    size_t base = ((size_t)b * 8) * 65536 + (size_t)y * 256 + x;
#pragma unroll
    for (int o = 0; o < 8; o++) out[base + (size_t)o * 65536] = v[o] * invs;
}

// ---------------------------------------------------------------------------
extern "C" void kernel_launch(void* const* d_in, const int* in_sizes, int n_in,
                              void* d_out, int out_size) {
    const float* x   = (const float*)d_in[0];
    const float* act = (const float*)d_in[1];
    const float* g[7]; const float* be[7];
    for (int i = 0; i < 7; i++) { g[i] = (const float*)d_in[16 + 2*i]; be[i] = (const float*)d_in[17 + 2*i]; }
    float* out = (float*)d_out;
    float *pA = nullptr, *pB = nullptr;
    cudaGetSymbolAddress((void**)&pA, g_A);
    cudaGetSymbolAddress((void**)&pB, g_B);

    // dynamic smem: 2*WB + 16*PSTRIDE*4
    const int SM2 = 2*25*16*36 + 16*2088*4;   // 162432
    const int SM3 = 2*25*32*36 + 16*1640*4;   // 162560
    const int SM4 = 2*25*32*36 + 16*1064*4;   // 125696
    const int SM5 = 2*25*64*36 + 16*1640*4;   // 220160
    const int SM6 = 2*25*64*36 + 16*1064*4;   // 183296
    cudaFuncSetAttribute(conv_mma<1,2,16,16,256>, cudaFuncAttributeMaxDynamicSharedMemorySize, SM2);
    cudaFuncSetAttribute(conv_mma<2,0,16,32,128>, cudaFuncAttributeMaxDynamicSharedMemorySize, SM3);
    cudaFuncSetAttribute(conv_mma<1,2,32,32,128>, cudaFuncAttributeMaxDynamicSharedMemorySize, SM4);
    cudaFuncSetAttribute(conv_mma<2,1,32,64,128>, cudaFuncAttributeMaxDynamicSharedMemorySize, SM5);
    cudaFuncSetAttribute(conv_mma<1,2,64,64,128>, cudaFuncAttributeMaxDynamicSharedMemorySize, SM6);

    const int rows[7] = {3200, 6400, 12800, 25600, 51200, 102400, 512};
    const int offs[7] = {0, 3200, 9600, 22400, 48000, 99200, 201600};
    for (int i = 0; i < 7; i++) {
        gen_weights<<<(rows[i] + 255) / 256, 256>>>(
            (const float*)d_in[2 + 2*i], (const float*)d_in[3 + 2*i], act, rows[i], offs[i]);
    }
    // weight images: wOff, Cout, Cin, imgOff
    prep_w<<<dim3(57,  NB), 256>>>(offs[2], 32, 16, 0);        // conv3
    prep_w<<<dim3(113, NB), 256>>>(offs[3], 32, 32, 57600);    // conv4
    prep_w<<<dim3(225, NB), 256>>>(offs[4], 64, 32, 172800);   // conv5
    prep_w<<<dim3(450, NB), 256>>>(offs[5], 64, 64, 403200);   // conv6
    prep_w<<<dim3(29,  NB), 256>>>(offs[1], 16, 16, 864000);   // conv2

    bn_stats<<<NB * 8, 256>>>(x, g[0], be[0], 8, 65536);
    conv5x5<2, 1><<<dim3(8, 8, NB), dim3(16, 16)>>>(x, pA, 8, 256, offs[0], 1);
    bn_stats<<<NB * 16, 256>>>(pA, g[1], be[1], 16, 65536);
    conv_mma<1,2,16,16,256><<<dim3(64, NB), 256, SM2>>>(pA, pB, 864000);
    bn_stats<<<NB * 16, 256>>>(pB, g[2], be[2], 16, 65536);
    pool_bn<<<(NB * 16 * 16384 + 255) / 256, 256>>>(pB, pA);

    conv_mma<2,0,16,32,128><<<dim3(32, NB), 256, SM3>>>(pA, pB, 0);
    bn_stats<<<NB * 32, 256>>>(pB, g[3], be[3], 32, 16384);
    conv_mma<1,2,32,32,128><<<dim3(32, NB), 256, SM4>>>(pB, pA, 57600);
    bn_stats<<<NB * 32, 256>>>(pA, g[4], be[4], 32, 16384);
    conv_mma<2,1,32,64,128><<<dim3(32, NB), 256, SM5>>>(pA, pB, 172800);
    bn_stats<<<NB * 64, 256>>>(pB, g[5], be[5], 64, 16384);
    conv_mma<1,2,64,64,128><<<dim3(32, NB), 256, SM6>>>(pB, pA, 403200);
    bn_stats<<<NB * 64, 256>>>(pA, g[6], be[6], 64, 16384);

    conv1x1<<<dim3(64, NB), 256>>>(pA, pB);
    up_softmax<<<(NB * 65536 + 255) / 256, 256>>>(pB, out);
}

// round 9
// speedup vs baseline: 1.8302x; 1.0118x over previous
#include <cuda_runtime.h>
#include <math.h>
#include <stdint.h>

#define NB 32
#define WTOT 202112
#define SAMP 892800

__device__ float g_y[NB * WTOT];
__device__ float g_A[NB * 1048576];
__device__ float g_B[NB * 1048576];
__device__ float g_stats[NB * 64 * 2];
__device__ unsigned char g_wimg[(size_t)NB * SAMP];  // per-sample bf16 hi/lo weight images

// ---------------- helpers ----------------
__device__ __forceinline__ uint16_t f2bf(float v) {
    uint16_t r; asm("cvt.rn.bf16.f32 %0, %1;" : "=h"(r) : "f"(v)); return r;
}
__device__ __forceinline__ uint32_t cvt2bf(float hi, float lo) {   // {hi | lo}
    uint32_t r; asm("cvt.rn.bf16x2.f32 %0, %1, %2;" : "=r"(r) : "f"(hi), "f"(lo)); return r;
}
__device__ __forceinline__ unsigned long long pack2(float lo, float hi) {
    unsigned long long r; asm("mov.b64 %0, {%1, %2};" : "=l"(r) : "f"(lo), "f"(hi)); return r;
}
__device__ __forceinline__ void ffma2(unsigned long long& d, unsigned long long a, unsigned long long b) {
    asm("fma.rn.f32x2 %0, %1, %2, %0;" : "+l"(d) : "l"(a), "l"(b));
}
__device__ __forceinline__ void unpack2(unsigned long long v, float& lo, float& hi) {
    asm("mov.b64 {%0, %1}, %2;" : "=f"(lo), "=f"(hi) : "l"(v));
}
__device__ __forceinline__ void mma16816(float* c, uint32_t a0, uint32_t a1, uint32_t a2, uint32_t a3,
                                         uint32_t b0, uint32_t b1) {
    asm volatile("mma.sync.aligned.m16n8k16.row.col.f32.bf16.bf16.f32 "
        "{%0,%1,%2,%3}, {%4,%5,%6,%7}, {%8,%9}, {%0,%1,%2,%3};"
        : "+f"(c[0]), "+f"(c[1]), "+f"(c[2]), "+f"(c[3])
        : "r"(a0), "r"(a1), "r"(a2), "r"(a3), "r"(b0), "r"(b1));
}

// ---------------- merged weight generation (all 7 linear layers) -----------
__global__ void gen_all(const float* __restrict__ W1, const float* __restrict__ B1,
                        const float* __restrict__ W2, const float* __restrict__ B2,
                        const float* __restrict__ W3, const float* __restrict__ B3,
                        const float* __restrict__ W4, const float* __restrict__ B4,
                        const float* __restrict__ W5, const float* __restrict__ B5,
                        const float* __restrict__ W6, const float* __restrict__ B6,
                        const float* __restrict__ W7, const float* __restrict__ B7,
                        const float* __restrict__ act) {
    __shared__ float sa[NB * 32];
    for (int i = threadIdx.x; i < NB * 32; i += blockDim.x) sa[i] = act[i];
    __syncthreads();
    int r = blockIdx.x * blockDim.x + threadIdx.x;
    if (r >= WTOT) return;
    const float* Wt; const float* bt; int local;
    if      (r < 3200)   { Wt = W1; bt = B1; local = r; }
    else if (r < 9600)   { Wt = W2; bt = B2; local = r - 3200; }
    else if (r < 22400)  { Wt = W3; bt = B3; local = r - 9600; }
    else if (r < 48000)  { Wt = W4; bt = B4; local = r - 22400; }
    else if (r < 99200)  { Wt = W5; bt = B5; local = r - 48000; }
    else if (r < 201600) { Wt = W6; bt = B6; local = r - 99200; }
    else                 { Wt = W7; bt = B7; local = r - 201600; }
    float w[32];
    const float4* wp = reinterpret_cast<const float4*>(Wt + (size_t)local * 32);
#pragma unroll
    for (int i = 0; i < 8; i++) { float4 v = wp[i]; w[4*i]=v.x; w[4*i+1]=v.y; w[4*i+2]=v.z; w[4*i+3]=v.w; }
    float bv = bt[local];
    for (int s = 0; s < NB; s++) {
        float acc = bv;
#pragma unroll
        for (int k = 0; k < 32; k++) acc = fmaf(w[k], sa[s*32+k], acc);
        g_y[(size_t)s * WTOT + r] = acc;
    }
}

// ---------------- merged weight image prep (5 mma layers) -------------------
// Image per (sample, layer): [chunk][ hi: [tap][cout][18ch] bf16 | lo: same ]
__global__ void prep_all() {
    // segments: {elems, wOff, Cout, Cin, imgOff}
    int e = blockIdx.x * 256 + threadIdx.x;
    int b = blockIdx.y;
    int wOff, Cout, Cin, imgOff;
    if      (e < 14400)  { wOff = 9600;   Cout = 32; Cin = 16; imgOff = 0;      }
    else if (e < 43200)  { wOff = 22400;  Cout = 32; Cin = 32; imgOff = 57600;  e -= 14400; }
    else if (e < 100800) { wOff = 48000;  Cout = 64; Cin = 32; imgOff = 172800; e -= 43200; }
    else if (e < 216000) { wOff = 99200;  Cout = 64; Cin = 64; imgOff = 403200; e -= 100800; }
    else if (e < 223200) { wOff = 3200;   Cout = 16; Cin = 16; imgOff = 864000; e -= 216000; }
    else return;
    int per = 25 * Cout * 18;
    int chunk = e / per; int rem = e - chunk * per;
    int tap = rem / (Cout * 18); int rem2 = rem - tap * Cout * 18;
    int cout = rem2 / 18; int cc = rem2 - cout * 18;
    float v = 0.f;
    if (cc < 16)
        v = g_y[(size_t)b * WTOT + wOff + ((size_t)cout * Cin + chunk * 16 + cc) * 25 + tap];
    uint16_t hb = f2bf(v);
    uint16_t lb = f2bf(v - __uint_as_float((uint32_t)hb << 16));
    int WBl = 25 * Cout * 36;
    size_t base = (size_t)b * SAMP + imgOff + (size_t)chunk * 2 * WBl
                + ((size_t)(tap * Cout + cout) * 18 + cc) * 2;
    *(uint16_t*)(g_wimg + base) = hb;
    *(uint16_t*)(g_wimg + base + WBl) = lb;
}

// ---------------- BN stats ----------------
__global__ void bn_stats(const float* __restrict__ src, const float* __restrict__ g,
                         const float* __restrict__ be, int C, int HW) {
    int plane = blockIdx.x;
    int c = plane % C;
    const float* p = src + (size_t)plane * HW;
    float s = 0.f, s2 = 0.f;
    for (int i = threadIdx.x; i < HW; i += 256) { float v = p[i]; s += v; s2 = fmaf(v, v, s2); }
    __shared__ float sh0[256], sh1[256];
    sh0[threadIdx.x] = s; sh1[threadIdx.x] = s2;
    __syncthreads();
    for (int ofs = 128; ofs > 0; ofs >>= 1) {
        if (threadIdx.x < ofs) { sh0[threadIdx.x] += sh0[threadIdx.x+ofs]; sh1[threadIdx.x] += sh1[threadIdx.x+ofs]; }
        __syncthreads();
    }
    if (threadIdx.x == 0) {
        float inv = 1.f / (float)HW;
        float m = sh0[0] * inv;
        float var = sh1[0] * inv - m * m;
        float sc = g[c] * rsqrtf(var + 1e-5f);
        g_stats[plane*2] = sc;
        g_stats[plane*2+1] = be[c] - m * sc;
    }
}

// ---------------- scalar conv (conv1 only, S=256, Cin=8) ----------------
template<int DIL, int MODE>
__global__ __launch_bounds__(256)
void conv5x5(const float* __restrict__ in, float* __restrict__ out,
             int Cin, int S, int wOff, int grps) {
    constexpr int PAD = 2 * DIL;
    constexpr int TIN = 32 + 4 * DIL;
    constexpr int RS  = 48;
    __shared__ float sm[TIN * RS];
    __shared__ __align__(8) float sw[25 * 16];
    int z = blockIdx.z;
    int b = z / grps, gq = z - b * grps;
    int gbase = gq * 16;
    int x0 = blockIdx.x * 32, y0 = blockIdx.y * 32;
    int tx = threadIdx.x, ty = threadIdx.y;
    int tid = ty * 16 + tx;
    unsigned long long acc[4][8];
#pragma unroll
    for (int p = 0; p < 4; p++)
#pragma unroll
        for (int j = 0; j < 8; j++) acc[p][j] = 0ULL;
    const float* wb = g_y + (size_t)b * WTOT + wOff;
    for (int c = 0; c < Cin; c++) {
        float sc = 1.f, sf = 0.f;
        if (MODE) { sc = g_stats[(b*Cin+c)*2]; sf = g_stats[(b*Cin+c)*2+1]; }
        const float* ip = in + ((size_t)(b * Cin + c)) * S * S;
        for (int i = tid; i < TIN * TIN; i += 256) {
            int r = i / TIN, col = i - r * TIN;
            int iy = y0 - PAD + r, ix = x0 - PAD + col;
            float v = 0.f;
            if (iy >= 0 && iy < S && ix >= 0 && ix < S) {
                v = ip[(size_t)iy * S + ix];
                if (MODE) { v = fmaf(v, sc, sf); if (MODE == 2) v = fmaxf(v, 0.f); }
            }
            sm[r * RS + col] = v;
        }
        for (int i = tid; i < 400; i += 256) {
            int k = i >> 4, gg = i & 15;
            sw[i] = wb[((size_t)(gbase + gg) * Cin + c) * 25 + k];
        }
        __syncthreads();
#pragma unroll 1
        for (int ky = 0; ky < 5; ky++) {
#pragma unroll
            for (int kx = 0; kx < 5; kx++) {
                int base = (ty + ky * DIL) * RS + tx + kx * DIL;
                unsigned long long T0 = pack2(sm[base], sm[base]);
                unsigned long long T1 = pack2(sm[base+16], sm[base+16]);
                unsigned long long T2 = pack2(sm[base+16*RS], sm[base+16*RS]);
                unsigned long long T3 = pack2(sm[base+16*RS+16], sm[base+16*RS+16]);
                const unsigned long long* wq = reinterpret_cast<const unsigned long long*>(sw + (ky*5+kx)*16);
#pragma unroll
                for (int j = 0; j < 8; j++) {
                    unsigned long long w2 = wq[j];
                    ffma2(acc[0][j], T0, w2); ffma2(acc[1][j], T1, w2);
                    ffma2(acc[2][j], T2, w2); ffma2(acc[3][j], T3, w2);
                }
            }
        }
        __syncthreads();
    }
    int Cout = grps * 16;
#pragma unroll
    for (int j = 0; j < 8; j++) {
        float e0, e1;
        float* op0 = out + ((size_t)(b * Cout + gbase + 2*j)) * S * S;
        float* op1 = op0 + (size_t)S * S;
        size_t o00 = (size_t)(y0 + ty) * S + x0 + tx;
        size_t o10 = (size_t)(y0 + ty + 16) * S + x0 + tx;
        unpack2(acc[0][j], e0, e1); op0[o00] = e0; op1[o00] = e1;
        unpack2(acc[1][j], e0, e1); op0[o00+16] = e0; op1[o00+16] = e1;
        unpack2(acc[2][j], e0, e1); op0[o10] = e0; op1[o10] = e1;
        unpack2(acc[3][j], e0, e1); op0[o10+16] = e0; op1[o10+16] = e1;
    }
}

// ---------------- mma.sync conv (convs 2-6) ---------------------------------
// CTA = (b, 4 output rows). 8 warps: warp w -> row y0+(w>>1), x-half (w&1)*(S/2),
// T = S/32 m16 tiles per warp. Split-bf16 3-pass, PASS-MAJOR ordering:
//   all (n,i) Ah*Bh -> all (n,i) Al*Bh -> reload B-lo -> all (n,i) Ah*Bl
// so each acc[i][n] is touched at reuse distance T*NN (no HMMA RAW chains).
template<int DIL, int MODE, int CIN, int COUT, int S>
__global__ __launch_bounds__(256, 1)
void conv_mma(const float* __restrict__ in, float* __restrict__ out, int imgOff) {
    constexpr int WB = 25 * COUT * 36;
    constexpr int NC = CIN / 16;
    constexpr int XP = S + 4 * DIL;
    constexpr int R  = 4 + 4 * DIL;
    constexpr int PS0 = R * XP;
    constexpr int PSTRIDE = PS0 + ((40 - (PS0 & 31)) & 31);
    constexpr int T  = S / 32;
    constexpr int NN = COUT / 8;
    extern __shared__ __align__(16) char dsm[];
    uint32_t* sStage = (uint32_t*)(dsm + 2 * WB);
    const int tid = threadIdx.x, w = tid >> 5, lane = tid & 31;
    const int g = lane >> 2, t = lane & 3;
    const int b = blockIdx.y, y0 = blockIdx.x * 4;
    const int ry = w >> 1, xseg = (w & 1) * (S / 2);
    float acc[T][NN][4];
#pragma unroll
    for (int i = 0; i < T; i++)
#pragma unroll
        for (int n = 0; n < NN; n++)
#pragma unroll
            for (int j = 0; j < 4; j++) acc[i][n][j] = 0.f;
    const unsigned char* img = g_wimg + (size_t)b * SAMP + imgOff;

#pragma unroll 1
    for (int chunk = 0; chunk < NC; chunk++) {
        __syncthreads();
        {   // copy pre-formatted weights (hi|lo)
            const uint4* src = (const uint4*)(img + (size_t)chunk * 2 * WB);
            uint4* dst = (uint4*)dsm;
            for (int i = tid; i < 2 * WB / 16; i += 256) dst[i] = src[i];
        }
        {   // stage 16 channels as bf16x2 pairs (hi p0-7, lo p8-15), BN folded
            int cb = chunk * 16;
            for (int idx = tid; idx < 8 * PS0; idx += 256) {
                int p = idx / PS0, rem = idx - p * PS0;
                int r = rem / XP, xp = rem - r * XP;
                int iy = y0 + r - 2 * DIL, ix = xp - 2 * DIL;
                float v0 = 0.f, v1 = 0.f;
                if (iy >= 0 && iy < S && ix >= 0 && ix < S) {
                    int c0 = cb + p * 2;
                    const float* bp = in + ((size_t)(b * CIN + c0)) * (S * S) + (size_t)iy * S + ix;
                    v0 = bp[0]; v1 = bp[(size_t)S * S];
                    if (MODE) {
                        v0 = fmaf(v0, g_stats[(b*CIN+c0)*2],   g_stats[(b*CIN+c0)*2+1]);
                        v1 = fmaf(v1, g_stats[(b*CIN+c0+1)*2], g_stats[(b*CIN+c0+1)*2+1]);
                        if (MODE == 2) { v0 = fmaxf(v0, 0.f); v1 = fmaxf(v1, 0.f); }
                    }
                }
                uint32_t hp = cvt2bf(v1, v0);
                float e0 = v0 - __uint_as_float(hp << 16);
                float e1 = v1 - __uint_as_float(hp & 0xffff0000u);
                uint32_t lp = cvt2bf(e1, e0);
                sStage[p * PSTRIDE + rem]       = hp;
                sStage[(8 + p) * PSTRIDE + rem] = lp;
            }
        }
        __syncthreads();
#pragma unroll 1
        for (int ky = 0; ky < 5; ky++) {
#pragma unroll 1
            for (int kx = 0; kx < 5; kx++) {
                int off = (ry + ky * DIL) * XP + xseg + kx * DIL + g;
                uint32_t ah[T][4], al[T][4];
#pragma unroll
                for (int i = 0; i < T; i++) {
                    int o = off + i * 16;
                    ah[i][0] = sStage[t * PSTRIDE + o];
                    ah[i][1] = sStage[t * PSTRIDE + o + 8];
                    ah[i][2] = sStage[(t + 4) * PSTRIDE + o];
                    ah[i][3] = sStage[(t + 4) * PSTRIDE + o + 8];
                    al[i][0] = sStage[(t + 8) * PSTRIDE + o];
                    al[i][1] = sStage[(t + 8) * PSTRIDE + o + 8];
                    al[i][2] = sStage[(t + 12) * PSTRIDE + o];
                    al[i][3] = sStage[(t + 12) * PSTRIDE + o + 8];
                }
                const char* wB = dsm + ((ky * 5 + kx) * COUT + g) * 36 + t * 4;
                uint32_t bb[NN][2];
#pragma unroll
                for (int n = 0; n < NN; n++) {
                    bb[n][0] = *(const uint32_t*)(wB + n * 288);
                    bb[n][1] = *(const uint32_t*)(wB + n * 288 + 16);
                }
                // pass 1: Ah * Bh
#pragma unroll
                for (int n = 0; n < NN; n++)
#pragma unroll
                    for (int i = 0; i < T; i++)
                        mma16816(acc[i][n], ah[i][0], ah[i][1], ah[i][2], ah[i][3], bb[n][0], bb[n][1]);
                // pass 2: Al * Bh
#pragma unroll
                for (int n = 0; n < NN; n++)
#pragma unroll
                    for (int i = 0; i < T; i++)
                        mma16816(acc[i][n], al[i][0], al[i][1], al[i][2], al[i][3], bb[n][0], bb[n][1]);
                // reload B-lo
#pragma unroll
                for (int n = 0; n < NN; n++) {
                    bb[n][0] = *(const uint32_t*)(wB + WB + n * 288);
                    bb[n][1] = *(const uint32_t*)(wB + WB + n * 288 + 16);
                }
                // pass 3: Ah * Bl
#pragma unroll
                for (int n = 0; n < NN; n++)
#pragma unroll
                    for (int i = 0; i < T; i++)
                        mma16816(acc[i][n], ah[i][0], ah[i][1], ah[i][2], ah[i][3], bb[n][0], bb[n][1]);
            }
        }
    }
    int row = y0 + ry;
    float* orow = out + ((size_t)b * COUT) * (S * S) + (size_t)row * S;
#pragma unroll
    for (int i = 0; i < T; i++) {
        int px = xseg + i * 16 + g;
#pragma unroll
        for (int n = 0; n < NN; n++) {
            float* p0 = orow + ((size_t)(n * 8 + 2 * t)) * (S * S);
            float* p1 = p0 + (size_t)S * S;
            p0[px]     = acc[i][n][0];
            p1[px]     = acc[i][n][1];
            p0[px + 8] = acc[i][n][2];
            p1[px + 8] = acc[i][n][3];
        }
    }
}

// ---------------- pool / 1x1 / upsample+softmax ----------------
__global__ void pool_bn(const float* __restrict__ in, float* __restrict__ out) {
    int idx = blockIdx.x * blockDim.x + threadIdx.x;
    if (idx >= NB * 16 * 128 * 128) return;
    int x = idx & 127, y = (idx >> 7) & 127, pc = idx >> 14;
    const float* ip = in + (size_t)pc * 65536;
    int o2 = (2 * y) * 256 + 2 * x;
    float v = (ip[o2] + ip[o2+1] + ip[o2+256] + ip[o2+257]) * 0.25f;
    out[idx] = fmaf(v, g_stats[pc*2], g_stats[pc*2+1]);
}

__global__ void conv1x1(const float* __restrict__ in, float* __restrict__ out) {
    __shared__ float sw[512];
    int b = blockIdx.y;
    const float* wb = g_y + (size_t)b * WTOT + 201600;
    for (int i = threadIdx.x; i < 512; i += blockDim.x) sw[i] = wb[i];
    __syncthreads();
    int pix = blockIdx.x * blockDim.x + threadIdx.x;
    if (pix >= 16384) return;
    float acc[8] = {0,0,0,0,0,0,0,0};
    for (int c = 0; c < 64; c++) {
        float v = in[((size_t)(b*64 + c)) * 16384 + pix];
        v = fmaf(v, g_stats[(b*64+c)*2], g_stats[(b*64+c)*2+1]);
#pragma unroll
        for (int o = 0; o < 8; o++) acc[o] = fmaf(v, sw[o*64 + c], acc[o]);
    }
#pragma unroll
    for (int o = 0; o < 8; o++) out[((size_t)(b*8 + o)) * 16384 + pix] = acc[o];
}

__global__ void up_softmax(const float* __restrict__ in, float* __restrict__ out) {
    int idx = blockIdx.x * blockDim.x + threadIdx.x;
    if (idx >= NB * 65536) return;
    int x = idx & 255, y = (idx >> 8) & 255, b = idx >> 16;
    const float r = 127.0f / 255.0f;
    float sy = y * r, sx = x * r;
    int y0 = (int)sy, x0 = (int)sx;
    int y1 = min(y0 + 1, 127), x1 = min(x0 + 1, 127);
    float wy = sy - (float)y0, wx = sx - (float)x0;
    const float* bp = in + (size_t)b * 8 * 16384;
    float v[8], m = -1e30f;
#pragma unroll
    for (int o = 0; o < 8; o++) {
        const float* p = bp + o * 16384;
        float a00 = p[y0*128+x0], a01 = p[y0*128+x1];
        float a10 = p[y1*128+x0], a11 = p[y1*128+x1];
        float t0 = a00 * (1.f - wy) + a10 * wy;
        float t1 = a01 * (1.f - wy) + a11 * wy;
        v[o] = t0 * (1.f - wx) + t1 * wx;
        m = fmaxf(m, v[o]);
    }
    float s = 0.f;
#pragma unroll
    for (int o = 0; o < 8; o++) { v[o] = expf(v[o] - m); s += v[o]; }
    float invs = 1.f / s;
    size_t base = ((size_t)b * 8) * 65536 + (size_t)y * 256 + x;
#pragma unroll
    for (int o = 0; o < 8; o++) out[base + (size_t)o * 65536] = v[o] * invs;
}

// ---------------------------------------------------------------------------
extern "C" void kernel_launch(void* const* d_in, const int* in_sizes, int n_in,
                              void* d_out, int out_size) {
    const float* x   = (const float*)d_in[0];
    const float* act = (const float*)d_in[1];
    const float* g[7]; const float* be[7];
    for (int i = 0; i < 7; i++) { g[i] = (const float*)d_in[16 + 2*i]; be[i] = (const float*)d_in[17 + 2*i]; }
    float* out = (float*)d_out;
    float *pA = nullptr, *pB = nullptr;
    cudaGetSymbolAddress((void**)&pA, g_A);
    cudaGetSymbolAddress((void**)&pB, g_B);

    // dynamic smem: 2*WB + 16*PSTRIDE*4
    const int SM2 = 2*25*16*36 + 16*2088*4;   // 162432
    const int SM3 = 2*25*32*36 + 16*1640*4;   // 162560
    const int SM4 = 2*25*32*36 + 16*1064*4;   // 125696
    const int SM5 = 2*25*64*36 + 16*1640*4;   // 220160
    const int SM6 = 2*25*64*36 + 16*1064*4;   // 183296
    cudaFuncSetAttribute(conv_mma<1,2,16,16,256>, cudaFuncAttributeMaxDynamicSharedMemorySize, SM2);
    cudaFuncSetAttribute(conv_mma<2,0,16,32,128>, cudaFuncAttributeMaxDynamicSharedMemorySize, SM3);
    cudaFuncSetAttribute(conv_mma<1,2,32,32,128>, cudaFuncAttributeMaxDynamicSharedMemorySize, SM4);
    cudaFuncSetAttribute(conv_mma<2,1,32,64,128>, cudaFuncAttributeMaxDynamicSharedMemorySize, SM5);
    cudaFuncSetAttribute(conv_mma<1,2,64,64,128>, cudaFuncAttributeMaxDynamicSharedMemorySize, SM6);

    const int offs[7] = {0, 3200, 9600, 22400, 48000, 99200, 201600};

    gen_all<<<(WTOT + 255) / 256, 256>>>(
        (const float*)d_in[2],  (const float*)d_in[3],
        (const float*)d_in[4],  (const float*)d_in[5],
        (const float*)d_in[6],  (const float*)d_in[7],
        (const float*)d_in[8],  (const float*)d_in[9],
        (const float*)d_in[10], (const float*)d_in[11],
        (const float*)d_in[12], (const float*)d_in[13],
        (const float*)d_in[14], (const float*)d_in[15], act);
    prep_all<<<dim3((223200 + 255) / 256, NB), 256>>>();

    bn_stats<<<NB * 8, 256>>>(x, g[0], be[0], 8, 65536);
    conv5x5<2, 1><<<dim3(8, 8, NB), dim3(16, 16)>>>(x, pA, 8, 256, offs[0], 1);
    bn_stats<<<NB * 16, 256>>>(pA, g[1], be[1], 16, 65536);
    conv_mma<1,2,16,16,256><<<dim3(64, NB), 256, SM2>>>(pA, pB, 864000);
    bn_stats<<<NB * 16, 256>>>(pB, g[2], be[2], 16, 65536);
    pool_bn<<<(NB * 16 * 16384 + 255) / 256, 256>>>(pB, pA);

    conv_mma<2,0,16,32,128><<<dim3(32, NB), 256, SM3>>>(pA, pB, 0);
    bn_stats<<<NB * 32, 256>>>(pB, g[3], be[3], 32, 16384);
    conv_mma<1,2,32,32,128><<<dim3(32, NB), 256, SM4>>>(pB, pA, 57600);
    bn_stats<<<NB * 32, 256>>>(pA, g[4], be[4], 32, 16384);
    conv_mma<2,1,32,64,128><<<dim3(32, NB), 256, SM5>>>(pA, pB, 172800);
    bn_stats<<<NB * 64, 256>>>(pB, g[5], be[5], 64, 16384);
    conv_mma<1,2,64,64,128><<<dim3(32, NB), 256, SM6>>>(pB, pA, 403200);
    bn_stats<<<NB * 64, 256>>>(pA, g[6], be[6], 64, 16384);

    conv1x1<<<dim3(64, NB), 256>>>(pA, pB);
    up_softmax<<<(NB * 65536 + 255) / 256, 256>>>(pB, out);
}

// round 10
// speedup vs baseline: 2.1091x; 1.1524x over previous
#include <cuda_runtime.h>
#include <cuda_fp16.h>
#include <math.h>
#include <stdint.h>

#define NB 32
#define WTOT 202112
#define SAMP 460800

__device__ float g_y[NB * WTOT];
__device__ float g_A[NB * 1048576];
__device__ float g_B[NB * 1048576];
__device__ float g_stats[NB * 64 * 2];
__device__ unsigned char g_wimg[(size_t)NB * SAMP];  // per-sample fp16 weight images

// ---------------- helpers ----------------
__device__ __forceinline__ uint16_t f2h(float v) {
    uint16_t r; asm("cvt.rn.f16.f32 %0, %1;" : "=h"(r) : "f"(v)); return r;
}
__device__ __forceinline__ uint32_t cvt2h(float hi, float lo) {   // {hi | lo} packed f16x2
    uint32_t r; asm("cvt.rn.f16x2.f32 %0, %1, %2;" : "=r"(r) : "f"(hi), "f"(lo)); return r;
}
__device__ __forceinline__ void mma16816(float* c, uint32_t a0, uint32_t a1, uint32_t a2, uint32_t a3,
                                         uint32_t b0, uint32_t b1) {
    asm volatile("mma.sync.aligned.m16n8k16.row.col.f32.f16.f16.f32 "
        "{%0,%1,%2,%3}, {%4,%5,%6,%7}, {%8,%9}, {%0,%1,%2,%3};"
        : "+f"(c[0]), "+f"(c[1]), "+f"(c[2]), "+f"(c[3])
        : "r"(a0), "r"(a1), "r"(a2), "r"(a3), "r"(b0), "r"(b1));
}

// ---------------- merged weight generation (all 7 linear layers) -----------
__global__ void gen_all(const float* __restrict__ W1, const float* __restrict__ B1,
                        const float* __restrict__ W2, const float* __restrict__ B2,
                        const float* __restrict__ W3, const float* __restrict__ B3,
                        const float* __restrict__ W4, const float* __restrict__ B4,
                        const float* __restrict__ W5, const float* __restrict__ B5,
                        const float* __restrict__ W6, const float* __restrict__ B6,
                        const float* __restrict__ W7, const float* __restrict__ B7,
                        const float* __restrict__ act) {
    __shared__ float sa[NB * 32];
    for (int i = threadIdx.x; i < NB * 32; i += blockDim.x) sa[i] = act[i];
    __syncthreads();
    int r = blockIdx.x * blockDim.x + threadIdx.x;
    if (r >= WTOT) return;
    const float* Wt; const float* bt; int local;
    if      (r < 3200)   { Wt = W1; bt = B1; local = r; }
    else if (r < 9600)   { Wt = W2; bt = B2; local = r - 3200; }
    else if (r < 22400)  { Wt = W3; bt = B3; local = r - 9600; }
    else if (r < 48000)  { Wt = W4; bt = B4; local = r - 22400; }
    else if (r < 99200)  { Wt = W5; bt = B5; local = r - 48000; }
    else if (r < 201600) { Wt = W6; bt = B6; local = r - 99200; }
    else                 { Wt = W7; bt = B7; local = r - 201600; }
    float w[32];
    const float4* wp = reinterpret_cast<const float4*>(Wt + (size_t)local * 32);
#pragma unroll
    for (int i = 0; i < 8; i++) { float4 v = wp[i]; w[4*i]=v.x; w[4*i+1]=v.y; w[4*i+2]=v.z; w[4*i+3]=v.w; }
    float bv = bt[local];
    for (int s = 0; s < NB; s++) {
        float acc = bv;
#pragma unroll
        for (int k = 0; k < 32; k++) acc = fmaf(w[k], sa[s*32+k], acc);
        g_y[(size_t)s * WTOT + r] = acc;
    }
}

// ---------------- merged weight image prep (6 mma layers, fp16) ------------
// Image per (sample, layer): [chunk][tap][cout][18ch] fp16
__global__ void prep_all() {
    int e = blockIdx.x * 256 + threadIdx.x;
    int b = blockIdx.y;
    int wOff, Cout, CinReal, imgOff;
    if      (e < 14400)  { wOff = 9600;   Cout = 32; CinReal = 16; imgOff = 0;      }
    else if (e < 43200)  { wOff = 22400;  Cout = 32; CinReal = 32; imgOff = 28800;  e -= 14400; }
    else if (e < 100800) { wOff = 48000;  Cout = 64; CinReal = 32; imgOff = 86400;  e -= 43200; }
    else if (e < 216000) { wOff = 99200;  Cout = 64; CinReal = 64; imgOff = 201600; e -= 100800; }
    else if (e < 223200) { wOff = 3200;   Cout = 16; CinReal = 16; imgOff = 432000; e -= 216000; }
    else if (e < 230400) { wOff = 0;      Cout = 16; CinReal = 8;  imgOff = 446400; e -= 223200; }
    else return;
    int per = 25 * Cout * 18;
    int chunk = e / per; int rem = e - chunk * per;
    int tap = rem / (Cout * 18); int rem2 = rem - tap * Cout * 18;
    int cout = rem2 / 18; int cc = rem2 - cout * 18;
    int cin = chunk * 16 + cc;
    float v = 0.f;
    if (cc < 16 && cin < CinReal)
        v = g_y[(size_t)b * WTOT + wOff + ((size_t)cout * CinReal + cin) * 25 + tap];
    size_t base = (size_t)b * SAMP + imgOff + (size_t)chunk * (25 * Cout * 36)
                + ((size_t)(tap * Cout + cout) * 18 + cc) * 2;
    *(uint16_t*)(g_wimg + base) = f2h(v);
}

// ---------------- BN stats ----------------
__global__ void bn_stats(const float* __restrict__ src, const float* __restrict__ g,
                         const float* __restrict__ be, int C, int HW) {
    int plane = blockIdx.x;
    int c = plane % C;
    const float* p = src + (size_t)plane * HW;
    float s = 0.f, s2 = 0.f;
    for (int i = threadIdx.x; i < HW; i += 256) { float v = p[i]; s += v; s2 = fmaf(v, v, s2); }
    __shared__ float sh0[256], sh1[256];
    sh0[threadIdx.x] = s; sh1[threadIdx.x] = s2;
    __syncthreads();
    for (int ofs = 128; ofs > 0; ofs >>= 1) {
        if (threadIdx.x < ofs) { sh0[threadIdx.x] += sh0[threadIdx.x+ofs]; sh1[threadIdx.x] += sh1[threadIdx.x+ofs]; }
        __syncthreads();
    }
    if (threadIdx.x == 0) {
        float inv = 1.f / (float)HW;
        float m = sh0[0] * inv;
        float var = sh1[0] * inv - m * m;
        float sc = g[c] * rsqrtf(var + 1e-5f);
        g_stats[plane*2] = sc;
        g_stats[plane*2+1] = be[c] - m * sc;
    }
}

// ---------------- mma.sync conv (ALL convs 1-6), split-fp16 2-pass ---------
// CTA = (b, 4 output rows). Warp w -> row y0+(w>>1), x-half (w&1)*(S/2).
// T = S/32 m16 tiles/warp. D += Ah*Bh + Al*Bh (A split to 22 bits, B fp16).
// Stage: u32 pairs [16][PSTRIDE], PSTRIDE % 32 == 8 -> conflict-free A LDS.
// CIN = padded channels (16k), CREAL = actual input channels.
template<int DIL, int MODE, int CIN, int CREAL, int COUT, int S>
__global__ __launch_bounds__(256, 1)
void conv_mma(const float* __restrict__ in, float* __restrict__ out, int imgOff) {
    constexpr int WB = 25 * COUT * 36;
    constexpr int NC = CIN / 16;
    constexpr int XP = S + 4 * DIL;
    constexpr int R  = 4 + 4 * DIL;
    constexpr int PS0 = R * XP;
    constexpr int PSTRIDE = PS0 + ((40 - (PS0 & 31)) & 31);
    constexpr int T  = S / 32;
    constexpr int NN = COUT / 8;
    extern __shared__ __align__(16) char dsm[];
    uint32_t* sStage = (uint32_t*)(dsm + WB);
    const int tid = threadIdx.x, w = tid >> 5, lane = tid & 31;
    const int g = lane >> 2, t = lane & 3;
    const int b = blockIdx.y, y0 = blockIdx.x * 4;
    const int ry = w >> 1, xseg = (w & 1) * (S / 2);
    float acc[T][NN][4];
#pragma unroll
    for (int i = 0; i < T; i++)
#pragma unroll
        for (int n = 0; n < NN; n++)
#pragma unroll
            for (int j = 0; j < 4; j++) acc[i][n][j] = 0.f;
    const unsigned char* img = g_wimg + (size_t)b * SAMP + imgOff;

#pragma unroll 1
    for (int chunk = 0; chunk < NC; chunk++) {
        __syncthreads();
        {   // copy pre-formatted fp16 weights
            const uint4* src = (const uint4*)(img + (size_t)chunk * WB);
            uint4* dst = (uint4*)dsm;
            for (int i = tid; i < WB / 16; i += 256) dst[i] = src[i];
        }
        {   // stage 16 channels as f16x2 pairs (hi p0-7, lo p8-15), BN folded
            int cb = chunk * 16;
            for (int idx = tid; idx < 8 * PS0; idx += 256) {
                int p = idx / PS0, rem = idx - p * PS0;
                int r = rem / XP, xp = rem - r * XP;
                int iy = y0 + r - 2 * DIL, ix = xp - 2 * DIL;
                int c0 = cb + p * 2;
                float v0 = 0.f, v1 = 0.f;
                if (iy >= 0 && iy < S && ix >= 0 && ix < S && c0 < CREAL) {
                    const float* bp = in + ((size_t)(b * CREAL + c0)) * (S * S) + (size_t)iy * S + ix;
                    v0 = bp[0]; v1 = bp[(size_t)S * S];
                    if (MODE) {
                        v0 = fmaf(v0, g_stats[(b*CREAL+c0)*2],   g_stats[(b*CREAL+c0)*2+1]);
                        v1 = fmaf(v1, g_stats[(b*CREAL+c0+1)*2], g_stats[(b*CREAL+c0+1)*2+1]);
                        if (MODE == 2) { v0 = fmaxf(v0, 0.f); v1 = fmaxf(v1, 0.f); }
                    }
                }
                uint32_t hp = cvt2h(v1, v0);
                __half2 hh = *reinterpret_cast<__half2*>(&hp);
                float2 bk = __half22float2(hh);          // bk.x = v0 approx, bk.y = v1 approx
                uint32_t lp = cvt2h(v1 - bk.y, v0 - bk.x);
                sStage[p * PSTRIDE + rem]       = hp;
                sStage[(8 + p) * PSTRIDE + rem] = lp;
            }
        }
        __syncthreads();
#pragma unroll 1
        for (int ky = 0; ky < 5; ky++) {
#pragma unroll 1
            for (int kx = 0; kx < 5; kx++) {
                int off = (ry + ky * DIL) * XP + xseg + kx * DIL + g;
                uint32_t ah[T][4], al[T][4];
#pragma unroll
                for (int i = 0; i < T; i++) {
                    int o = off + i * 16;
                    ah[i][0] = sStage[t * PSTRIDE + o];
                    ah[i][1] = sStage[t * PSTRIDE + o + 8];
                    ah[i][2] = sStage[(t + 4) * PSTRIDE + o];
                    ah[i][3] = sStage[(t + 4) * PSTRIDE + o + 8];
                    al[i][0] = sStage[(t + 8) * PSTRIDE + o];
                    al[i][1] = sStage[(t + 8) * PSTRIDE + o + 8];
                    al[i][2] = sStage[(t + 12) * PSTRIDE + o];
                    al[i][3] = sStage[(t + 12) * PSTRIDE + o + 8];
                }
                const char* wB = dsm + ((ky * 5 + kx) * COUT + g) * 36 + t * 4;
                uint32_t bb[NN][2];
#pragma unroll
                for (int n = 0; n < NN; n++) {
                    bb[n][0] = *(const uint32_t*)(wB + n * 288);
                    bb[n][1] = *(const uint32_t*)(wB + n * 288 + 16);
                }
                // pass 1: Ah * B
#pragma unroll
                for (int n = 0; n < NN; n++)
#pragma unroll
                    for (int i = 0; i < T; i++)
                        mma16816(acc[i][n], ah[i][0], ah[i][1], ah[i][2], ah[i][3], bb[n][0], bb[n][1]);
                // pass 2: Al * B
#pragma unroll
                for (int n = 0; n < NN; n++)
#pragma unroll
                    for (int i = 0; i < T; i++)
                        mma16816(acc[i][n], al[i][0], al[i][1], al[i][2], al[i][3], bb[n][0], bb[n][1]);
            }
        }
    }
    int row = y0 + ry;
    float* orow = out + ((size_t)b * COUT) * (S * S) + (size_t)row * S;
#pragma unroll
    for (int i = 0; i < T; i++) {
        int px = xseg + i * 16 + g;
#pragma unroll
        for (int n = 0; n < NN; n++) {
            float* p0 = orow + ((size_t)(n * 8 + 2 * t)) * (S * S);
            float* p1 = p0 + (size_t)S * S;
            p0[px]     = acc[i][n][0];
            p1[px]     = acc[i][n][1];
            p0[px + 8] = acc[i][n][2];
            p1[px + 8] = acc[i][n][3];
        }
    }
}

// ---------------- pool / 1x1 / upsample+softmax ----------------
__global__ void pool_bn(const float* __restrict__ in, float* __restrict__ out) {
    int idx = blockIdx.x * blockDim.x + threadIdx.x;
    if (idx >= NB * 16 * 128 * 128) return;
    int x = idx & 127, y = (idx >> 7) & 127, pc = idx >> 14;
    const float* ip = in + (size_t)pc * 65536;
    int o2 = (2 * y) * 256 + 2 * x;
    float v = (ip[o2] + ip[o2+1] + ip[o2+256] + ip[o2+257]) * 0.25f;
    out[idx] = fmaf(v, g_stats[pc*2], g_stats[pc*2+1]);
}

__global__ void conv1x1(const float* __restrict__ in, float* __restrict__ out) {
    __shared__ float sw[512];
    int b = blockIdx.y;
    const float* wb = g_y + (size_t)b * WTOT + 201600;
    for (int i = threadIdx.x; i < 512; i += blockDim.x) sw[i] = wb[i];
    __syncthreads();
    int pix = blockIdx.x * blockDim.x + threadIdx.x;
    if (pix >= 16384) return;
    float acc[8] = {0,0,0,0,0,0,0,0};
    for (int c = 0; c < 64; c++) {
        float v = in[((size_t)(b*64 + c)) * 16384 + pix];
        v = fmaf(v, g_stats[(b*64+c)*2], g_stats[(b*64+c)*2+1]);
#pragma unroll
        for (int o = 0; o < 8; o++) acc[o] = fmaf(v, sw[o*64 + c], acc[o]);
    }
#pragma unroll
    for (int o = 0; o < 8; o++) out[((size_t)(b*8 + o)) * 16384 + pix] = acc[o];
}

__global__ void up_softmax(const float* __restrict__ in, float* __restrict__ out) {
    int idx = blockIdx.x * blockDim.x + threadIdx.x;
    if (idx >= NB * 65536) return;
    int x = idx & 255, y = (idx >> 8) & 255, b = idx >> 16;
    const float r = 127.0f / 255.0f;
    float sy = y * r, sx = x * r;
    int y0 = (int)sy, x0 = (int)sx;
    int y1 = min(y0 + 1, 127), x1 = min(x0 + 1, 127);
    float wy = sy - (float)y0, wx = sx - (float)x0;
    const float* bp = in + (size_t)b * 8 * 16384;
    float v[8], m = -1e30f;
#pragma unroll
    for (int o = 0; o < 8; o++) {
        const float* p = bp + o * 16384;
        float a00 = p[y0*128+x0], a01 = p[y0*128+x1];
        float a10 = p[y1*128+x0], a11 = p[y1*128+x1];
        float t0 = a00 * (1.f - wy) + a10 * wy;
        float t1 = a01 * (1.f - wy) + a11 * wy;
        v[o] = t0 * (1.f - wx) + t1 * wx;
        m = fmaxf(m, v[o]);
    }
    float s = 0.f;
#pragma unroll
    for (int o = 0; o < 8; o++) { v[o] = expf(v[o] - m); s += v[o]; }
    float invs = 1.f / s;
    size_t base = ((size_t)b * 8) * 65536 + (size_t)y * 256 + x;
#pragma unroll
    for (int o = 0; o < 8; o++) out[base + (size_t)o * 65536] = v[o] * invs;
}

// ---------------------------------------------------------------------------
extern "C" void kernel_launch(void* const* d_in, const int* in_sizes, int n_in,
                              void* d_out, int out_size) {
    const float* x   = (const float*)d_in[0];
    const float* act = (const float*)d_in[1];
    const float* g[7]; const float* be[7];
    for (int i = 0; i < 7; i++) { g[i] = (const float*)d_in[16 + 2*i]; be[i] = (const float*)d_in[17 + 2*i]; }
    float* out = (float*)d_out;
    float *pA = nullptr, *pB = nullptr;
    cudaGetSymbolAddress((void**)&pA, g_A);
    cudaGetSymbolAddress((void**)&pB, g_B);

    // dynamic smem: WB + 16*PSTRIDE*4
    const int SM1 = 25*16*36 + 16*3176*4;   // 217664 (S=256, dil2)
    const int SM2 = 25*16*36 + 16*2088*4;   // 148032 (S=256, dil1)
    const int SM3 = 25*32*36 + 16*1640*4;   // 133760 (S=128, dil2)
    const int SM4 = 25*32*36 + 16*1064*4;   //  96896 (S=128, dil1)
    const int SM5 = 25*64*36 + 16*1640*4;   // 162560
    const int SM6 = 25*64*36 + 16*1064*4;   // 125696
    cudaFuncSetAttribute(conv_mma<2,1,16,8, 16,256>, cudaFuncAttributeMaxDynamicSharedMemorySize, SM1);
    cudaFuncSetAttribute(conv_mma<1,2,16,16,16,256>, cudaFuncAttributeMaxDynamicSharedMemorySize, SM2);
    cudaFuncSetAttribute(conv_mma<2,0,16,16,32,128>, cudaFuncAttributeMaxDynamicSharedMemorySize, SM3);
    cudaFuncSetAttribute(conv_mma<1,2,32,32,32,128>, cudaFuncAttributeMaxDynamicSharedMemorySize, SM4);
    cudaFuncSetAttribute(conv_mma<2,1,32,32,64,128>, cudaFuncAttributeMaxDynamicSharedMemorySize, SM5);
    cudaFuncSetAttribute(conv_mma<1,2,64,64,64,128>, cudaFuncAttributeMaxDynamicSharedMemorySize, SM6);

    gen_all<<<(WTOT + 255) / 256, 256>>>(
        (const float*)d_in[2],  (const float*)d_in[3],
        (const float*)d_in[4],  (const float*)d_in[5],
        (const float*)d_in[6],  (const float*)d_in[7],
        (const float*)d_in[8],  (const float*)d_in[9],
        (const float*)d_in[10], (const float*)d_in[11],
        (const float*)d_in[12], (const float*)d_in[13],
        (const float*)d_in[14], (const float*)d_in[15], act);
    prep_all<<<dim3((230400 + 255) / 256, NB), 256>>>();

    bn_stats<<<NB * 8, 256>>>(x, g[0], be[0], 8, 65536);
    conv_mma<2,1,16,8, 16,256><<<dim3(64, NB), 256, SM1>>>(x, pA, 446400);
    bn_stats<<<NB * 16, 256>>>(pA, g[1], be[1], 16, 65536);
    conv_mma<1,2,16,16,16,256><<<dim3(64, NB), 256, SM2>>>(pA, pB, 432000);
    bn_stats<<<NB * 16, 256>>>(pB, g[2], be[2], 16, 65536);
    pool_bn<<<(NB * 16 * 16384 + 255) / 256, 256>>>(pB, pA);

    conv_mma<2,0,16,16,32,128><<<dim3(32, NB), 256, SM3>>>(pA, pB, 0);
    bn_stats<<<NB * 32, 256>>>(pB, g[3], be[3], 32, 16384);
    conv_mma<1,2,32,32,32,128><<<dim3(32, NB), 256, SM4>>>(pB, pA, 28800);
    bn_stats<<<NB * 32, 256>>>(pA, g[4], be[4], 32, 16384);
    conv_mma<2,1,32,32,64,128><<<dim3(32, NB), 256, SM5>>>(pA, pB, 86400);
    bn_stats<<<NB * 64, 256>>>(pB, g[5], be[5], 64, 16384);
    conv_mma<1,2,64,64,64,128><<<dim3(32, NB), 256, SM6>>>(pB, pA, 201600);
    bn_stats<<<NB * 64, 256>>>(pA, g[6], be[6], 64, 16384);

    conv1x1<<<dim3(64, NB), 256>>>(pA, pB);
    up_softmax<<<(NB * 65536 + 255) / 256, 256>>>(pB, out);
}

// round 11
// speedup vs baseline: 2.1095x; 1.0002x over previous
#include <cuda_runtime.h>
#include <cuda_fp16.h>
#include <math.h>
#include <stdint.h>

#define NB 32
#define WTOT 202112
#define SAMP 460800

__device__ float g_y[NB * WTOT];
__device__ float g_A[NB * 1048576];
__device__ float g_B[NB * 1048576];
__device__ float g_stats[NB * 64 * 2];
__device__ unsigned char g_wimg[(size_t)NB * SAMP];  // per-sample fp16 weight images

// ---------------- helpers ----------------
__device__ __forceinline__ uint16_t f2h(float v) {
    uint16_t r; asm("cvt.rn.f16.f32 %0, %1;" : "=h"(r) : "f"(v)); return r;
}
__device__ __forceinline__ uint32_t cvt2h(float hi, float lo) {   // {hi | lo} packed f16x2
    uint32_t r; asm("cvt.rn.f16x2.f32 %0, %1, %2;" : "=r"(r) : "f"(hi), "f"(lo)); return r;
}
__device__ __forceinline__ void mma16816(float* c, uint32_t a0, uint32_t a1, uint32_t a2, uint32_t a3,
                                         uint32_t b0, uint32_t b1) {
    asm volatile("mma.sync.aligned.m16n8k16.row.col.f32.f16.f16.f32 "
        "{%0,%1,%2,%3}, {%4,%5,%6,%7}, {%8,%9}, {%0,%1,%2,%3};"
        : "+f"(c[0]), "+f"(c[1]), "+f"(c[2]), "+f"(c[3])
        : "r"(a0), "r"(a1), "r"(a2), "r"(a3), "r"(b0), "r"(b1));
}

// ---------------- merged weight generation (all 7 linear layers) -----------
__global__ void gen_all(const float* __restrict__ W1, const float* __restrict__ B1,
                        const float* __restrict__ W2, const float* __restrict__ B2,
                        const float* __restrict__ W3, const float* __restrict__ B3,
                        const float* __restrict__ W4, const float* __restrict__ B4,
                        const float* __restrict__ W5, const float* __restrict__ B5,
                        const float* __restrict__ W6, const float* __restrict__ B6,
                        const float* __restrict__ W7, const float* __restrict__ B7,
                        const float* __restrict__ act) {
    __shared__ float sa[NB * 32];
    for (int i = threadIdx.x; i < NB * 32; i += blockDim.x) sa[i] = act[i];
    __syncthreads();
    int r = blockIdx.x * blockDim.x + threadIdx.x;
    if (r >= WTOT) return;
    const float* Wt; const float* bt; int local;
    if      (r < 3200)   { Wt = W1; bt = B1; local = r; }
    else if (r < 9600)   { Wt = W2; bt = B2; local = r - 3200; }
    else if (r < 22400)  { Wt = W3; bt = B3; local = r - 9600; }
    else if (r < 48000)  { Wt = W4; bt = B4; local = r - 22400; }
    else if (r < 99200)  { Wt = W5; bt = B5; local = r - 48000; }
    else if (r < 201600) { Wt = W6; bt = B6; local = r - 99200; }
    else                 { Wt = W7; bt = B7; local = r - 201600; }
    float w[32];
    const float4* wp = reinterpret_cast<const float4*>(Wt + (size_t)local * 32);
#pragma unroll
    for (int i = 0; i < 8; i++) { float4 v = wp[i]; w[4*i]=v.x; w[4*i+1]=v.y; w[4*i+2]=v.z; w[4*i+3]=v.w; }
    float bv = bt[local];
    for (int s = 0; s < NB; s++) {
        float acc = bv;
#pragma unroll
        for (int k = 0; k < 32; k++) acc = fmaf(w[k], sa[s*32+k], acc);
        g_y[(size_t)s * WTOT + r] = acc;
    }
}

// ---------------- merged weight image prep (6 mma layers, fp16) ------------
// Image per (sample, layer): [chunk][tap][cout][18ch] fp16
__global__ void prep_all() {
    int e = blockIdx.x * 256 + threadIdx.x;
    int b = blockIdx.y;
    int wOff, Cout, CinReal, imgOff;
    if      (e < 14400)  { wOff = 9600;   Cout = 32; CinReal = 16; imgOff = 0;      }
    else if (e < 43200)  { wOff = 22400;  Cout = 32; CinReal = 32; imgOff = 28800;  e -= 14400; }
    else if (e < 100800) { wOff = 48000;  Cout = 64; CinReal = 32; imgOff = 86400;  e -= 43200; }
    else if (e < 216000) { wOff = 99200;  Cout = 64; CinReal = 64; imgOff = 201600; e -= 100800; }
    else if (e < 223200) { wOff = 3200;   Cout = 16; CinReal = 16; imgOff = 432000; e -= 216000; }
    else if (e < 230400) { wOff = 0;      Cout = 16; CinReal = 8;  imgOff = 446400; e -= 223200; }
    else return;
    int per = 25 * Cout * 18;
    int chunk = e / per; int rem = e - chunk * per;
    int tap = rem / (Cout * 18); int rem2 = rem - tap * Cout * 18;
    int cout = rem2 / 18; int cc = rem2 - cout * 18;
    int cin = chunk * 16 + cc;
    float v = 0.f;
    if (cc < 16 && cin < CinReal)
        v = g_y[(size_t)b * WTOT + wOff + ((size_t)cout * CinReal + cin) * 25 + tap];
    size_t base = (size_t)b * SAMP + imgOff + (size_t)chunk * (25 * Cout * 36)
                + ((size_t)(tap * Cout + cout) * 18 + cc) * 2;
    *(uint16_t*)(g_wimg + base) = f2h(v);
}

// ---------------- BN stats ----------------
__global__ void bn_stats(const float* __restrict__ src, const float* __restrict__ g,
                         const float* __restrict__ be, int C, int HW) {
    int plane = blockIdx.x;
    int c = plane % C;
    const float* p = src + (size_t)plane * HW;
    float s = 0.f, s2 = 0.f;
    for (int i = threadIdx.x; i < HW; i += 256) { float v = p[i]; s += v; s2 = fmaf(v, v, s2); }
    __shared__ float sh0[256], sh1[256];
    sh0[threadIdx.x] = s; sh1[threadIdx.x] = s2;
    __syncthreads();
    for (int ofs = 128; ofs > 0; ofs >>= 1) {
        if (threadIdx.x < ofs) { sh0[threadIdx.x] += sh0[threadIdx.x+ofs]; sh1[threadIdx.x] += sh1[threadIdx.x+ofs]; }
        __syncthreads();
    }
    if (threadIdx.x == 0) {
        float inv = 1.f / (float)HW;
        float m = sh0[0] * inv;
        float var = sh1[0] * inv - m * m;
        float sc = g[c] * rsqrtf(var + 1e-5f);
        g_stats[plane*2] = sc;
        g_stats[plane*2+1] = be[c] - m * sc;
    }
}

// ---------------- mma.sync conv (ALL convs 1-6), split-fp16 2-pass ---------
// CTA = (b, 4 output rows). Warp w -> row y0+(w>>1), x-half (w&1)*(S/2).
// T = S/32 m16 tiles/warp. D += Ah*Bh + Al*Bh (A split to 22 bits, B fp16).
// Stage: u32 pairs [16][PSTRIDE], PSTRIDE % 32 == 8 -> conflict-free A LDS.
// CIN = padded channels (16k), CREAL = actual input channels.
template<int DIL, int MODE, int CIN, int CREAL, int COUT, int S>
__global__ __launch_bounds__(256, 1)
void conv_mma(const float* __restrict__ in, float* __restrict__ out, int imgOff) {
    constexpr int WB = 25 * COUT * 36;
    constexpr int NC = CIN / 16;
    constexpr int XP = S + 4 * DIL;
    constexpr int R  = 4 + 4 * DIL;
    constexpr int PS0 = R * XP;
    constexpr int PSTRIDE = PS0 + ((40 - (PS0 & 31)) & 31);
    constexpr int T  = S / 32;
    constexpr int NN = COUT / 8;
    extern __shared__ __align__(16) char dsm[];
    uint32_t* sStage = (uint32_t*)(dsm + WB);
    const int tid = threadIdx.x, w = tid >> 5, lane = tid & 31;
    const int g = lane >> 2, t = lane & 3;
    const int b = blockIdx.y, y0 = blockIdx.x * 4;
    const int ry = w >> 1, xseg = (w & 1) * (S / 2);
    float acc[T][NN][4];
#pragma unroll
    for (int i = 0; i < T; i++)
#pragma unroll
        for (int n = 0; n < NN; n++)
#pragma unroll
            for (int j = 0; j < 4; j++) acc[i][n][j] = 0.f;
    const unsigned char* img = g_wimg + (size_t)b * SAMP + imgOff;

#pragma unroll 1
    for (int chunk = 0; chunk < NC; chunk++) {
        __syncthreads();
        {   // copy pre-formatted fp16 weights
            const uint4* src = (const uint4*)(img + (size_t)chunk * WB);
            uint4* dst = (uint4*)dsm;
            for (int i = tid; i < WB / 16; i += 256) dst[i] = src[i];
        }
        {   // stage 16 channels as f16x2 pairs (hi p0-7, lo p8-15), BN folded
            int cb = chunk * 16;
            for (int idx = tid; idx < 8 * PS0; idx += 256) {
                int p = idx / PS0, rem = idx - p * PS0;
                int r = rem / XP, xp = rem - r * XP;
                int iy = y0 + r - 2 * DIL, ix = xp - 2 * DIL;
                int c0 = cb + p * 2;
                float v0 = 0.f, v1 = 0.f;
                if (iy >= 0 && iy < S && ix >= 0 && ix < S && c0 < CREAL) {
                    const float* bp = in + ((size_t)(b * CREAL + c0)) * (S * S) + (size_t)iy * S + ix;
                    v0 = bp[0]; v1 = bp[(size_t)S * S];
                    if (MODE) {
                        v0 = fmaf(v0, g_stats[(b*CREAL+c0)*2],   g_stats[(b*CREAL+c0)*2+1]);
                        v1 = fmaf(v1, g_stats[(b*CREAL+c0+1)*2], g_stats[(b*CREAL+c0+1)*2+1]);
                        if (MODE == 2) { v0 = fmaxf(v0, 0.f); v1 = fmaxf(v1, 0.f); }
                    }
                }
                uint32_t hp = cvt2h(v1, v0);
                __half2 hh = *reinterpret_cast<__half2*>(&hp);
                float2 bk = __half22float2(hh);          // bk.x = v0 approx, bk.y = v1 approx
                uint32_t lp = cvt2h(v1 - bk.y, v0 - bk.x);
                sStage[p * PSTRIDE + rem]       = hp;
                sStage[(8 + p) * PSTRIDE + rem] = lp;
            }
        }
        __syncthreads();
#pragma unroll 1
        for (int ky = 0; ky < 5; ky++) {
#pragma unroll 1
            for (int kx = 0; kx < 5; kx++) {
                int off = (ry + ky * DIL) * XP + xseg + kx * DIL + g;
                uint32_t ah[T][4], al[T][4];
#pragma unroll
                for (int i = 0; i < T; i++) {
                    int o = off + i * 16;
                    ah[i][0] = sStage[t * PSTRIDE + o];
                    ah[i][1] = sStage[t * PSTRIDE + o + 8];
                    ah[i][2] = sStage[(t + 4) * PSTRIDE + o];
                    ah[i][3] = sStage[(t + 4) * PSTRIDE + o + 8];
                    al[i][0] = sStage[(t + 8) * PSTRIDE + o];
                    al[i][1] = sStage[(t + 8) * PSTRIDE + o + 8];
                    al[i][2] = sStage[(t + 12) * PSTRIDE + o];
                    al[i][3] = sStage[(t + 12) * PSTRIDE + o + 8];
                }
                const char* wB = dsm + ((ky * 5 + kx) * COUT + g) * 36 + t * 4;
                uint32_t bb[NN][2];
#pragma unroll
                for (int n = 0; n < NN; n++) {
                    bb[n][0] = *(const uint32_t*)(wB + n * 288);
                    bb[n][1] = *(const uint32_t*)(wB + n * 288 + 16);
                }
                // pass 1: Ah * B
#pragma unroll
                for (int n = 0; n < NN; n++)
#pragma unroll
                    for (int i = 0; i < T; i++)
                        mma16816(acc[i][n], ah[i][0], ah[i][1], ah[i][2], ah[i][3], bb[n][0], bb[n][1]);
                // pass 2: Al * B
#pragma unroll
                for (int n = 0; n < NN; n++)
#pragma unroll
                    for (int i = 0; i < T; i++)
                        mma16816(acc[i][n], al[i][0], al[i][1], al[i][2], al[i][3], bb[n][0], bb[n][1]);
            }
        }
    }
    int row = y0 + ry;
    float* orow = out + ((size_t)b * COUT) * (S * S) + (size_t)row * S;
#pragma unroll
    for (int i = 0; i < T; i++) {
        int px = xseg + i * 16 + g;
#pragma unroll
        for (int n = 0; n < NN; n++) {
            float* p0 = orow + ((size_t)(n * 8 + 2 * t)) * (S * S);
            float* p1 = p0 + (size_t)S * S;
            p0[px]     = acc[i][n][0];
            p1[px]     = acc[i][n][1];
            p0[px + 8] = acc[i][n][2];
            p1[px + 8] = acc[i][n][3];
        }
    }
}

// ---------------- pool / 1x1 / upsample+softmax ----------------
__global__ void pool_bn(const float* __restrict__ in, float* __restrict__ out) {
    int idx = blockIdx.x * blockDim.x + threadIdx.x;
    if (idx >= NB * 16 * 128 * 128) return;
    int x = idx & 127, y = (idx >> 7) & 127, pc = idx >> 14;
    const float* ip = in + (size_t)pc * 65536;
    int o2 = (2 * y) * 256 + 2 * x;
    float v = (ip[o2] + ip[o2+1] + ip[o2+256] + ip[o2+257]) * 0.25f;
    out[idx] = fmaf(v, g_stats[pc*2], g_stats[pc*2+1]);
}

__global__ void conv1x1(const float* __restrict__ in, float* __restrict__ out) {
    __shared__ float sw[512];
    int b = blockIdx.y;
    const float* wb = g_y + (size_t)b * WTOT + 201600;
    for (int i = threadIdx.x; i < 512; i += blockDim.x) sw[i] = wb[i];
    __syncthreads();
    int pix = blockIdx.x * blockDim.x + threadIdx.x;
    if (pix >= 16384) return;
    float acc[8] = {0,0,0,0,0,0,0,0};
    for (int c = 0; c < 64; c++) {
        float v = in[((size_t)(b*64 + c)) * 16384 + pix];
        v = fmaf(v, g_stats[(b*64+c)*2], g_stats[(b*64+c)*2+1]);
#pragma unroll
        for (int o = 0; o < 8; o++) acc[o] = fmaf(v, sw[o*64 + c], acc[o]);
    }
#pragma unroll
    for (int o = 0; o < 8; o++) out[((size_t)(b*8 + o)) * 16384 + pix] = acc[o];
}

__global__ void up_softmax(const float* __restrict__ in, float* __restrict__ out) {
    int idx = blockIdx.x * blockDim.x + threadIdx.x;
    if (idx >= NB * 65536) return;
    int x = idx & 255, y = (idx >> 8) & 255, b = idx >> 16;
    const float r = 127.0f / 255.0f;
    float sy = y * r, sx = x * r;
    int y0 = (int)sy, x0 = (int)sx;
    int y1 = min(y0 + 1, 127), x1 = min(x0 + 1, 127);
    float wy = sy - (float)y0, wx = sx - (float)x0;
    const float* bp = in + (size_t)b * 8 * 16384;
    float v[8], m = -1e30f;
#pragma unroll
    for (int o = 0; o < 8; o++) {
        const float* p = bp + o * 16384;
        float a00 = p[y0*128+x0], a01 = p[y0*128+x1];
        float a10 = p[y1*128+x0], a11 = p[y1*128+x1];
        float t0 = a00 * (1.f - wy) + a10 * wy;
        float t1 = a01 * (1.f - wy) + a11 * wy;
        v[o] = t0 * (1.f - wx) + t1 * wx;
        m = fmaxf(m, v[o]);
    }
    float s = 0.f;
#pragma unroll
    for (int o = 0; o < 8; o++) { v[o] = expf(v[o] - m); s += v[o]; }
    float invs = 1.f / s;
    size_t base = ((size_t)b * 8) * 65536 + (size_t)y * 256 + x;
#pragma unroll
    for (int o = 0; o < 8; o++) out[base + (size_t)o * 65536] = v[o] * invs;
}

// ---------------------------------------------------------------------------
extern "C" void kernel_launch(void* const* d_in, const int* in_sizes, int n_in,
                              void* d_out, int out_size) {
    const float* x   = (const float*)d_in[0];
    const float* act = (const float*)d_in[1];
    const float* g[7]; const float* be[7];
    for (int i = 0; i < 7; i++) { g[i] = (const float*)d_in[16 + 2*i]; be[i] = (const float*)d_in[17 + 2*i]; }
    float* out = (float*)d_out;
    float *pA = nullptr, *pB = nullptr;
    cudaGetSymbolAddress((void**)&pA, g_A);
    cudaGetSymbolAddress((void**)&pB, g_B);

    // dynamic smem: WB + 16*PSTRIDE*4
    const int SM1 = 25*16*36 + 16*3176*4;   // 217664 (S=256, dil2)
    const int SM2 = 25*16*36 + 16*2088*4;   // 148032 (S=256, dil1)
    const int SM3 = 25*32*36 + 16*1640*4;   // 133760 (S=128, dil2)
    const int SM4 = 25*32*36 + 16*1064*4;   //  96896 (S=128, dil1)
    const int SM5 = 25*64*36 + 16*1640*4;   // 162560
    const int SM6 = 25*64*36 + 16*1064*4;   // 125696
    cudaFuncSetAttribute(conv_mma<2,1,16,8, 16,256>, cudaFuncAttributeMaxDynamicSharedMemorySize, SM1);
    cudaFuncSetAttribute(conv_mma<1,2,16,16,16,256>, cudaFuncAttributeMaxDynamicSharedMemorySize, SM2);
    cudaFuncSetAttribute(conv_mma<2,0,16,16,32,128>, cudaFuncAttributeMaxDynamicSharedMemorySize, SM3);
    cudaFuncSetAttribute(conv_mma<1,2,32,32,32,128>, cudaFuncAttributeMaxDynamicSharedMemorySize, SM4);
    cudaFuncSetAttribute(conv_mma<2,1,32,32,64,128>, cudaFuncAttributeMaxDynamicSharedMemorySize, SM5);
    cudaFuncSetAttribute(conv_mma<1,2,64,64,64,128>, cudaFuncAttributeMaxDynamicSharedMemorySize, SM6);

    gen_all<<<(WTOT + 255) / 256, 256>>>(
        (const float*)d_in[2],  (const float*)d_in[3],
        (const float*)d_in[4],  (const float*)d_in[5],
        (const float*)d_in[6],  (const float*)d_in[7],
        (const float*)d_in[8],  (const float*)d_in[9],
        (const float*)d_in[10], (const float*)d_in[11],
        (const float*)d_in[12], (const float*)d_in[13],
        (const float*)d_in[14], (const float*)d_in[15], act);
    prep_all<<<dim3((230400 + 255) / 256, NB), 256>>>();

    bn_stats<<<NB * 8, 256>>>(x, g[0], be[0], 8, 65536);
    conv_mma<2,1,16,8, 16,256><<<dim3(64, NB), 256, SM1>>>(x, pA, 446400);
    bn_stats<<<NB * 16, 256>>>(pA, g[1], be[1], 16, 65536);
    conv_mma<1,2,16,16,16,256><<<dim3(64, NB), 256, SM2>>>(pA, pB, 432000);
    bn_stats<<<NB * 16, 256>>>(pB, g[2], be[2], 16, 65536);
    pool_bn<<<(NB * 16 * 16384 + 255) / 256, 256>>>(pB, pA);

    conv_mma<2,0,16,16,32,128><<<dim3(32, NB), 256, SM3>>>(pA, pB, 0);
    bn_stats<<<NB * 32, 256>>>(pB, g[3], be[3], 32, 16384);
    conv_mma<1,2,32,32,32,128><<<dim3(32, NB), 256, SM4>>>(pB, pA, 28800);
    bn_stats<<<NB * 32, 256>>>(pA, g[4], be[4], 32, 16384);
    conv_mma<2,1,32,32,64,128><<<dim3(32, NB), 256, SM5>>>(pA, pB, 86400);
    bn_stats<<<NB * 64, 256>>>(pB, g[5], be[5], 64, 16384);
    conv_mma<1,2,64,64,64,128><<<dim3(32, NB), 256, SM6>>>(pB, pA, 201600);
    bn_stats<<<NB * 64, 256>>>(pA, g[6], be[6], 64, 16384);

    conv1x1<<<dim3(64, NB), 256>>>(pA, pB);
    up_softmax<<<(NB * 65536 + 255) / 256, 256>>>(pB, out);
}

// round 12
// speedup vs baseline: 3.2238x; 1.5282x over previous
#include <cuda_runtime.h>
#include <cuda_fp16.h>
#include <math.h>
#include <stdint.h>

#define NB 32
#define WTOT 202112
#define SAMP 460800

__device__ float g_y[NB * WTOT];
__device__ float g_A[NB * 1048576];
__device__ float g_B[NB * 1048576];
__device__ float g_stats[NB * 64 * 2];
__device__ unsigned char g_wimg[(size_t)NB * SAMP];  // per-sample fp16 weight images

// ---------------- helpers ----------------
__device__ __forceinline__ uint16_t f2h(float v) {
    uint16_t r; asm("cvt.rn.f16.f32 %0, %1;" : "=h"(r) : "f"(v)); return r;
}
__device__ __forceinline__ uint32_t cvt2h(float hi, float lo) {   // {hi | lo} packed f16x2
    uint32_t r; asm("cvt.rn.f16x2.f32 %0, %1, %2;" : "=r"(r) : "f"(hi), "f"(lo)); return r;
}
__device__ __forceinline__ void mma16816(float* c, uint32_t a0, uint32_t a1, uint32_t a2, uint32_t a3,
                                         uint32_t b0, uint32_t b1) {
    asm volatile("mma.sync.aligned.m16n8k16.row.col.f32.f16.f16.f32 "
        "{%0,%1,%2,%3}, {%4,%5,%6,%7}, {%8,%9}, {%0,%1,%2,%3};"
        : "+f"(c[0]), "+f"(c[1]), "+f"(c[2]), "+f"(c[3])
        : "r"(a0), "r"(a1), "r"(a2), "r"(a3), "r"(b0), "r"(b1));
}

// ---------------- merged weight generation (all 7 linear layers) -----------
__global__ void gen_all(const float* __restrict__ W1, const float* __restrict__ B1,
                        const float* __restrict__ W2, const float* __restrict__ B2,
                        const float* __restrict__ W3, const float* __restrict__ B3,
                        const float* __restrict__ W4, const float* __restrict__ B4,
                        const float* __restrict__ W5, const float* __restrict__ B5,
                        const float* __restrict__ W6, const float* __restrict__ B6,
                        const float* __restrict__ W7, const float* __restrict__ B7,
                        const float* __restrict__ act) {
    __shared__ float sa[NB * 32];
    for (int i = threadIdx.x; i < NB * 32; i += blockDim.x) sa[i] = act[i];
    __syncthreads();
    int r = blockIdx.x * blockDim.x + threadIdx.x;
    if (r >= WTOT) return;
    const float* Wt; const float* bt; int local;
    if      (r < 3200)   { Wt = W1; bt = B1; local = r; }
    else if (r < 9600)   { Wt = W2; bt = B2; local = r - 3200; }
    else if (r < 22400)  { Wt = W3; bt = B3; local = r - 9600; }
    else if (r < 48000)  { Wt = W4; bt = B4; local = r - 22400; }
    else if (r < 99200)  { Wt = W5; bt = B5; local = r - 48000; }
    else if (r < 201600) { Wt = W6; bt = B6; local = r - 99200; }
    else                 { Wt = W7; bt = B7; local = r - 201600; }
    float w[32];
    const float4* wp = reinterpret_cast<const float4*>(Wt + (size_t)local * 32);
#pragma unroll
    for (int i = 0; i < 8; i++) { float4 v = wp[i]; w[4*i]=v.x; w[4*i+1]=v.y; w[4*i+2]=v.z; w[4*i+3]=v.w; }
    float bv = bt[local];
    for (int s = 0; s < NB; s++) {
        float acc = bv;
#pragma unroll
        for (int k = 0; k < 32; k++) acc = fmaf(w[k], sa[s*32+k], acc);
        g_y[(size_t)s * WTOT + r] = acc;
    }
}

// ---------------- merged weight image prep (fp16) --------------------------
// Layers 2-6: [chunk][tap][cout][18ch] fp16.
// Layer 1 (tap-paired): [chunk13][cout16][18k] where k0-7 = tap 2q ch0-7,
//                       k8-15 = tap 2q+1 ch0-7 (zeros past tap 24).
__global__ void prep_all() {
    int e = blockIdx.x * 256 + threadIdx.x;
    int b = blockIdx.y;
    if (e >= 226944) return;
    if (e >= 223200) {                       // conv1 paired image
        e -= 223200;                         // 13*16*18 = 3744 entries
        int chunk = e / 288; int rem = e - chunk * 288;
        int cout = rem / 18, kk = rem - cout * 18;
        float v = 0.f;
        if (kk < 16) {
            int tap = 2 * chunk + (kk >> 3);
            int ch = kk & 7;
            if (tap < 25)
                v = g_y[(size_t)b * WTOT + ((size_t)cout * 8 + ch) * 25 + tap];
        }
        *(uint16_t*)(g_wimg + (size_t)b * SAMP + 446400
                     + (size_t)chunk * 576 + ((size_t)cout * 18 + kk) * 2) = f2h(v);
        return;
    }
    int wOff, Cout, CinReal, imgOff;
    if      (e < 14400)  { wOff = 9600;   Cout = 32; CinReal = 16; imgOff = 0;      }
    else if (e < 43200)  { wOff = 22400;  Cout = 32; CinReal = 32; imgOff = 28800;  e -= 14400; }
    else if (e < 100800) { wOff = 48000;  Cout = 64; CinReal = 32; imgOff = 86400;  e -= 43200; }
    else if (e < 216000) { wOff = 99200;  Cout = 64; CinReal = 64; imgOff = 201600; e -= 100800; }
    else                 { wOff = 3200;   Cout = 16; CinReal = 16; imgOff = 432000; e -= 216000; }
    int per = 25 * Cout * 18;
    int chunk = e / per; int rem = e - chunk * per;
    int tap = rem / (Cout * 18); int rem2 = rem - tap * Cout * 18;
    int cout = rem2 / 18; int cc = rem2 - cout * 18;
    int cin = chunk * 16 + cc;
    float v = 0.f;
    if (cc < 16 && cin < CinReal)
        v = g_y[(size_t)b * WTOT + wOff + ((size_t)cout * CinReal + cin) * 25 + tap];
    size_t base = (size_t)b * SAMP + imgOff + (size_t)chunk * (25 * Cout * 36)
                + ((size_t)(tap * Cout + cout) * 18 + cc) * 2;
    *(uint16_t*)(g_wimg + base) = f2h(v);
}

// ---------------- BN stats ----------------
__global__ void bn_stats(const float* __restrict__ src, const float* __restrict__ g,
                         const float* __restrict__ be, int C, int HW) {
    int plane = blockIdx.x;
    int c = plane % C;
    const float* p = src + (size_t)plane * HW;
    float s = 0.f, s2 = 0.f;
    for (int i = threadIdx.x; i < HW; i += 256) { float v = p[i]; s += v; s2 = fmaf(v, v, s2); }
    __shared__ float sh0[256], sh1[256];
    sh0[threadIdx.x] = s; sh1[threadIdx.x] = s2;
    __syncthreads();
    for (int ofs = 128; ofs > 0; ofs >>= 1) {
        if (threadIdx.x < ofs) { sh0[threadIdx.x] += sh0[threadIdx.x+ofs]; sh1[threadIdx.x] += sh1[threadIdx.x+ofs]; }
        __syncthreads();
    }
    if (threadIdx.x == 0) {
        float inv = 1.f / (float)HW;
        float m = sh0[0] * inv;
        float var = sh1[0] * inv - m * m;
        float sc = g[c] * rsqrtf(var + 1e-5f);
        g_stats[plane*2] = sc;
        g_stats[plane*2+1] = be[c] - m * sc;
    }
}

// ---------------- mma.sync conv (convs 2-6), x-tiled ------------------------
// CTA = (b, 4 output rows, XTILE cols). Warp w -> row (w>>1), x-half (w&1).
// T = XTILE/32 m16 tiles/warp. D += Ah*B + Al*B (A split to 22 bits, B fp16).
template<int DIL, int MODE, int CIN, int CREAL, int COUT, int S, int XTILE>
__global__ __launch_bounds__(256)
void conv_mma(const float* __restrict__ in, float* __restrict__ out, int imgOff) {
    constexpr int WB = 25 * COUT * 36;
    constexpr int NC = CIN / 16;
    constexpr int XP = XTILE + 4 * DIL;
    constexpr int R  = 4 + 4 * DIL;
    constexpr int PS0 = R * XP;
    constexpr int PSTRIDE = PS0 + ((40 - (PS0 & 31)) & 31);
    constexpr int T  = XTILE / 32;
    constexpr int NN = COUT / 8;
    constexpr int NXT = S / XTILE;
    extern __shared__ __align__(16) char dsm[];
    uint32_t* sStage = (uint32_t*)(dsm + WB);
    const int tid = threadIdx.x, w = tid >> 5, lane = tid & 31;
    const int g = lane >> 2, t = lane & 3;
    const int b = blockIdx.y;
    const int xt = blockIdx.x % NXT, yt = blockIdx.x / NXT;
    const int y0 = yt * 4, x0 = xt * XTILE;
    const int ry = w >> 1, xseg = (w & 1) * (XTILE / 2);
    float acc[T][NN][4];
#pragma unroll
    for (int i = 0; i < T; i++)
#pragma unroll
        for (int n = 0; n < NN; n++)
#pragma unroll
            for (int j = 0; j < 4; j++) acc[i][n][j] = 0.f;
    const unsigned char* img = g_wimg + (size_t)b * SAMP + imgOff;

#pragma unroll 1
    for (int chunk = 0; chunk < NC; chunk++) {
        __syncthreads();
        {   // copy pre-formatted fp16 weights
            const uint4* src = (const uint4*)(img + (size_t)chunk * WB);
            uint4* dst = (uint4*)dsm;
            for (int i = tid; i < WB / 16; i += 256) dst[i] = src[i];
        }
        {   // stage 16 channels as f16x2 pairs (hi p0-7, lo p8-15), BN folded
            int cb = chunk * 16;
            for (int idx = tid; idx < 8 * PS0; idx += 256) {
                int p = idx / PS0, rem = idx - p * PS0;
                int r = rem / XP, xp = rem - r * XP;
                int iy = y0 + r - 2 * DIL, ix = x0 + xp - 2 * DIL;
                int c0 = cb + p * 2;
                float v0 = 0.f, v1 = 0.f;
                if (iy >= 0 && iy < S && ix >= 0 && ix < S && c0 < CREAL) {
                    const float* bp = in + ((size_t)(b * CREAL + c0)) * (S * S) + (size_t)iy * S + ix;
                    v0 = bp[0]; v1 = bp[(size_t)S * S];
                    if (MODE) {
                        v0 = fmaf(v0, g_stats[(b*CREAL+c0)*2],   g_stats[(b*CREAL+c0)*2+1]);
                        v1 = fmaf(v1, g_stats[(b*CREAL+c0+1)*2], g_stats[(b*CREAL+c0+1)*2+1]);
                        if (MODE == 2) { v0 = fmaxf(v0, 0.f); v1 = fmaxf(v1, 0.f); }
                    }
                }
                uint32_t hp = cvt2h(v1, v0);
                __half2 hh = *reinterpret_cast<__half2*>(&hp);
                float2 bk = __half22float2(hh);
                uint32_t lp = cvt2h(v1 - bk.y, v0 - bk.x);
                sStage[p * PSTRIDE + rem]       = hp;
                sStage[(8 + p) * PSTRIDE + rem] = lp;
            }
        }
        __syncthreads();
#pragma unroll 1
        for (int ky = 0; ky < 5; ky++) {
#pragma unroll 1
            for (int kx = 0; kx < 5; kx++) {
                int off = (ry + ky * DIL) * XP + xseg + kx * DIL + g;
                uint32_t ah[T][4], al[T][4];
#pragma unroll
                for (int i = 0; i < T; i++) {
                    int o = off + i * 16;
                    ah[i][0] = sStage[t * PSTRIDE + o];
                    ah[i][1] = sStage[t * PSTRIDE + o + 8];
                    ah[i][2] = sStage[(t + 4) * PSTRIDE + o];
                    ah[i][3] = sStage[(t + 4) * PSTRIDE + o + 8];
                    al[i][0] = sStage[(t + 8) * PSTRIDE + o];
                    al[i][1] = sStage[(t + 8) * PSTRIDE + o + 8];
                    al[i][2] = sStage[(t + 12) * PSTRIDE + o];
                    al[i][3] = sStage[(t + 12) * PSTRIDE + o + 8];
                }
                const char* wB = dsm + ((ky * 5 + kx) * COUT + g) * 36 + t * 4;
                uint32_t bb[NN][2];
#pragma unroll
                for (int n = 0; n < NN; n++) {
                    bb[n][0] = *(const uint32_t*)(wB + n * 288);
                    bb[n][1] = *(const uint32_t*)(wB + n * 288 + 16);
                }
#pragma unroll
                for (int n = 0; n < NN; n++)
#pragma unroll
                    for (int i = 0; i < T; i++)
                        mma16816(acc[i][n], ah[i][0], ah[i][1], ah[i][2], ah[i][3], bb[n][0], bb[n][1]);
#pragma unroll
                for (int n = 0; n < NN; n++)
#pragma unroll
                    for (int i = 0; i < T; i++)
                        mma16816(acc[i][n], al[i][0], al[i][1], al[i][2], al[i][3], bb[n][0], bb[n][1]);
            }
        }
    }
    int row = y0 + ry;
    float* orow = out + ((size_t)b * COUT) * (S * S) + (size_t)row * S;
#pragma unroll
    for (int i = 0; i < T; i++) {
        int px = x0 + xseg + i * 16 + g;
#pragma unroll
        for (int n = 0; n < NN; n++) {
            float* p0 = orow + ((size_t)(n * 8 + 2 * t)) * (S * S);
            float* p1 = p0 + (size_t)S * S;
            p0[px]     = acc[i][n][0];
            p1[px]     = acc[i][n][1];
            p0[px + 8] = acc[i][n][2];
            p1[px + 8] = acc[i][n][3];
        }
    }
}

// ---------------- conv1: tap-paired k16 (8 real channels x 2 taps) ---------
// S=256, dil=2, COUT=16, XTILE=128. 13 k16 chunks; stage once (8 planes).
__global__ __launch_bounds__(256)
void conv1_mma(const float* __restrict__ in, float* __restrict__ out, int imgOff) {
    constexpr int S = 256, XTILE = 128, XP = 136, PS0 = 12 * 136;  // 1632
    constexpr int PSTRIDE = 1640, T = 4, NN = 2;
    extern __shared__ __align__(16) char dsm[];
    uint32_t* sStage = (uint32_t*)(dsm + 7488);
    const int tid = threadIdx.x, w = tid >> 5, lane = tid & 31;
    const int g = lane >> 2, t = lane & 3;
    const int b = blockIdx.y;
    const int xt = blockIdx.x & 1, yt = blockIdx.x >> 1;
    const int y0 = yt * 4, x0 = xt * XTILE;
    const int ry = w >> 1, xseg = (w & 1) * 64;
    float acc[T][NN][4];
#pragma unroll
    for (int i = 0; i < T; i++)
#pragma unroll
        for (int n = 0; n < NN; n++)
#pragma unroll
            for (int j = 0; j < 4; j++) acc[i][n][j] = 0.f;
    const unsigned char* img = g_wimg + (size_t)b * SAMP + imgOff;
    {   // copy weights: 13 chunks x 16 couts x 18k x 2B = 7488
        const uint4* src = (const uint4*)img;
        uint4* dst = (uint4*)dsm;
        for (int i = tid; i < 468; i += 256) dst[i] = src[i];
    }
    {   // stage 8 channels (4 hi pair-planes + 4 lo), BN(stats0) folded
        for (int idx = tid; idx < 4 * PS0; idx += 256) {
            int p = idx / PS0, rem = idx - p * PS0;
            int r = rem / XP, xp = rem - r * XP;
            int iy = y0 + r - 4, ix = x0 + xp - 4;
            int c0 = p * 2;
            float v0 = 0.f, v1 = 0.f;
            if (iy >= 0 && iy < S && ix >= 0 && ix < S) {
                const float* bp = in + ((size_t)(b * 8 + c0)) * 65536 + (size_t)iy * S + ix;
                v0 = bp[0]; v1 = bp[65536];
                v0 = fmaf(v0, g_stats[(b*8+c0)*2],   g_stats[(b*8+c0)*2+1]);
                v1 = fmaf(v1, g_stats[(b*8+c0+1)*2], g_stats[(b*8+c0+1)*2+1]);
            }
            uint32_t hp = cvt2h(v1, v0);
            __half2 hh = *reinterpret_cast<__half2*>(&hp);
            float2 bk = __half22float2(hh);
            uint32_t lp = cvt2h(v1 - bk.y, v0 - bk.x);
            sStage[p * PSTRIDE + rem]       = hp;
            sStage[(4 + p) * PSTRIDE + rem] = lp;
        }
    }
    __syncthreads();
#pragma unroll 1
    for (int q = 0; q < 13; q++) {
        int tap1 = 2 * q, tap2 = (2 * q + 1 < 25) ? 2 * q + 1 : 24;
        int ky1 = tap1 / 5, kx1 = tap1 - ky1 * 5;
        int ky2 = tap2 / 5, kx2 = tap2 - ky2 * 5;
        int o1 = (ry + ky1 * 2) * XP + xseg + kx1 * 2 + g;
        int o2 = (ry + ky2 * 2) * XP + xseg + kx2 * 2 + g;
        uint32_t ah[T][4], al[T][4];
#pragma unroll
        for (int i = 0; i < T; i++) {
            int p1 = o1 + i * 16, p2 = o2 + i * 16;
            ah[i][0] = sStage[t * PSTRIDE + p1];
            ah[i][1] = sStage[t * PSTRIDE + p1 + 8];
            ah[i][2] = sStage[t * PSTRIDE + p2];
            ah[i][3] = sStage[t * PSTRIDE + p2 + 8];
            al[i][0] = sStage[(t + 4) * PSTRIDE + p1];
            al[i][1] = sStage[(t + 4) * PSTRIDE + p1 + 8];
            al[i][2] = sStage[(t + 4) * PSTRIDE + p2];
            al[i][3] = sStage[(t + 4) * PSTRIDE + p2 + 8];
        }
        const char* wB = dsm + (q * 16 + g) * 36 + t * 4;
        uint32_t bb[NN][2];
#pragma unroll
        for (int n = 0; n < NN; n++) {
            bb[n][0] = *(const uint32_t*)(wB + n * 288);
            bb[n][1] = *(const uint32_t*)(wB + n * 288 + 16);
        }
#pragma unroll
        for (int n = 0; n < NN; n++)
#pragma unroll
            for (int i = 0; i < T; i++)
                mma16816(acc[i][n], ah[i][0], ah[i][1], ah[i][2], ah[i][3], bb[n][0], bb[n][1]);
#pragma unroll
        for (int n = 0; n < NN; n++)
#pragma unroll
            for (int i = 0; i < T; i++)
                mma16816(acc[i][n], al[i][0], al[i][1], al[i][2], al[i][3], bb[n][0], bb[n][1]);
    }
    int row = y0 + ry;
    float* orow = out + ((size_t)b * 16) * 65536 + (size_t)row * S;
#pragma unroll
    for (int i = 0; i < T; i++) {
        int px = x0 + xseg + i * 16 + g;
#pragma unroll
        for (int n = 0; n < NN; n++) {
            float* p0 = orow + ((size_t)(n * 8 + 2 * t)) * 65536;
            float* p1 = p0 + 65536;
            p0[px]     = acc[i][n][0];
            p1[px]     = acc[i][n][1];
            p0[px + 8] = acc[i][n][2];
            p1[px + 8] = acc[i][n][3];
        }
    }
}

// ---------------- pool / 1x1 / upsample+softmax ----------------
__global__ void pool_bn(const float* __restrict__ in, float* __restrict__ out) {
    int idx = blockIdx.x * blockDim.x + threadIdx.x;
    if (idx >= NB * 16 * 128 * 128) return;
    int x = idx & 127, y = (idx >> 7) & 127, pc = idx >> 14;
    const float* ip = in + (size_t)pc * 65536;
    int o2 = (2 * y) * 256 + 2 * x;
    float v = (ip[o2] + ip[o2+1] + ip[o2+256] + ip[o2+257]) * 0.25f;
    out[idx] = fmaf(v, g_stats[pc*2], g_stats[pc*2+1]);
}

__global__ void conv1x1(const float* __restrict__ in, float* __restrict__ out) {
    __shared__ float sw[512];
    int b = blockIdx.y;
    const float* wb = g_y + (size_t)b * WTOT + 201600;
    for (int i = threadIdx.x; i < 512; i += blockDim.x) sw[i] = wb[i];
    __syncthreads();
    int pix = blockIdx.x * blockDim.x + threadIdx.x;
    if (pix >= 16384) return;
    float acc[8] = {0,0,0,0,0,0,0,0};
    for (int c = 0; c < 64; c++) {
        float v = in[((size_t)(b*64 + c)) * 16384 + pix];
        v = fmaf(v, g_stats[(b*64+c)*2], g_stats[(b*64+c)*2+1]);
#pragma unroll
        for (int o = 0; o < 8; o++) acc[o] = fmaf(v, sw[o*64 + c], acc[o]);
    }
#pragma unroll
    for (int o = 0; o < 8; o++) out[((size_t)(b*8 + o)) * 16384 + pix] = acc[o];
}

__global__ void up_softmax(const float* __restrict__ in, float* __restrict__ out) {
    int idx = blockIdx.x * blockDim.x + threadIdx.x;
    if (idx >= NB * 65536) return;
    int x = idx & 255, y = (idx >> 8) & 255, b = idx >> 16;
    const float r = 127.0f / 255.0f;
    float sy = y * r, sx = x * r;
    int y0 = (int)sy, x0 = (int)sx;
    int y1 = min(y0 + 1, 127), x1 = min(x0 + 1, 127);
    float wy = sy - (float)y0, wx = sx - (float)x0;
    const float* bp = in + (size_t)b * 8 * 16384;
    float v[8], m = -1e30f;
#pragma unroll
    for (int o = 0; o < 8; o++) {
        const float* p = bp + o * 16384;
        float a00 = p[y0*128+x0], a01 = p[y0*128+x1];
        float a10 = p[y1*128+x0], a11 = p[y1*128+x1];
        float t0 = a00 * (1.f - wy) + a10 * wy;
        float t1 = a01 * (1.f - wy) + a11 * wy;
        v[o] = t0 * (1.f - wx) + t1 * wx;
        m = fmaxf(m, v[o]);
    }
    float s = 0.f;
#pragma unroll
    for (int o = 0; o < 8; o++) { v[o] = expf(v[o] - m); s += v[o]; }
    float invs = 1.f / s;
    size_t base = ((size_t)b * 8) * 65536 + (size_t)y * 256 + x;
#pragma unroll
    for (int o = 0; o < 8; o++) out[base + (size_t)o * 65536] = v[o] * invs;
}

// ---------------------------------------------------------------------------
extern "C" void kernel_launch(void* const* d_in, const int* in_sizes, int n_in,
                              void* d_out, int out_size) {
    const float* x   = (const float*)d_in[0];
    const float* act = (const float*)d_in[1];
    const float* g[7]; const float* be[7];
    for (int i = 0; i < 7; i++) { g[i] = (const float*)d_in[16 + 2*i]; be[i] = (const float*)d_in[17 + 2*i]; }
    float* out = (float*)d_out;
    float *pA = nullptr, *pB = nullptr;
    cudaGetSymbolAddress((void**)&pA, g_A);
    cudaGetSymbolAddress((void**)&pB, g_B);

    // dynamic smem
    const int SM1 = 7488  + 8  * 1640 * 4;  //  59968 -> 3 CTAs/SM
    const int SM2 = 14400 + 16 * 1064 * 4;  //  82496 -> 2
    const int SM3 = 28800 + 16 * 872  * 4;  //  84608 -> 2
    const int SM4 = 28800 + 16 * 552  * 4;  //  64128 -> 3
    const int SM5 = 57600 + 16 * 872  * 4;  // 113408 -> 2
    const int SM6 = 57600 + 16 * 552  * 4;  //  92928 -> 2
    cudaFuncSetAttribute(conv1_mma,                   cudaFuncAttributeMaxDynamicSharedMemorySize, SM1);
    cudaFuncSetAttribute(conv_mma<1,2,16,16,16,256,128>, cudaFuncAttributeMaxDynamicSharedMemorySize, SM2);
    cudaFuncSetAttribute(conv_mma<2,0,16,16,32,128,64>,  cudaFuncAttributeMaxDynamicSharedMemorySize, SM3);
    cudaFuncSetAttribute(conv_mma<1,2,32,32,32,128,64>,  cudaFuncAttributeMaxDynamicSharedMemorySize, SM4);
    cudaFuncSetAttribute(conv_mma<2,1,32,32,64,128,64>,  cudaFuncAttributeMaxDynamicSharedMemorySize, SM5);
    cudaFuncSetAttribute(conv_mma<1,2,64,64,64,128,64>,  cudaFuncAttributeMaxDynamicSharedMemorySize, SM6);

    gen_all<<<(WTOT + 255) / 256, 256>>>(
        (const float*)d_in[2],  (const float*)d_in[3],
        (const float*)d_in[4],  (const float*)d_in[5],
        (const float*)d_in[6],  (const float*)d_in[7],
        (const float*)d_in[8],  (const float*)d_in[9],
        (const float*)d_in[10], (const float*)d_in[11],
        (const float*)d_in[12], (const float*)d_in[13],
        (const float*)d_in[14], (const float*)d_in[15], act);
    prep_all<<<dim3((226944 + 255) / 256, NB), 256>>>();

    bn_stats<<<NB * 8, 256>>>(x, g[0], be[0], 8, 65536);
    conv1_mma<<<dim3(128, NB), 256, SM1>>>(x, pA, 446400);
    bn_stats<<<NB * 16, 256>>>(pA, g[1], be[1], 16, 65536);
    conv_mma<1,2,16,16,16,256,128><<<dim3(128, NB), 256, SM2>>>(pA, pB, 432000);
    bn_stats<<<NB * 16, 256>>>(pB, g[2], be[2], 16, 65536);
    pool_bn<<<(NB * 16 * 16384 + 255) / 256, 256>>>(pB, pA);

    conv_mma<2,0,16,16,32,128,64><<<dim3(64, NB), 256, SM3>>>(pA, pB, 0);
    bn_stats<<<NB * 32, 256>>>(pB, g[3], be[3], 32, 16384);
    conv_mma<1,2,32,32,32,128,64><<<dim3(64, NB), 256, SM4>>>(pB, pA, 28800);
    bn_stats<<<NB * 32, 256>>>(pA, g[4], be[4], 32, 16384);
    conv_mma<2,1,32,32,64,128,64><<<dim3(64, NB), 256, SM5>>>(pA, pB, 86400);
    bn_stats<<<NB * 64, 256>>>(pB, g[5], be[5], 64, 16384);
    conv_mma<1,2,64,64,64,128,64><<<dim3(64, NB), 256, SM6>>>(pB, pA, 201600);
    bn_stats<<<NB * 64, 256>>>(pA, g[6], be[6], 64, 16384);

    conv1x1<<<dim3(64, NB), 256>>>(pA, pB);
    up_softmax<<<(NB * 65536 + 255) / 256, 256>>>(pB, out);
}

// round 13
// speedup vs baseline: 3.2420x; 1.0057x over previous
#include <cuda_runtime.h>
#include <cuda_fp16.h>
#include <math.h>
#include <stdint.h>

#define NB 32
#define WTOT 202112
#define SAMP 460800

__device__ float g_y[NB * WTOT];
__device__ float g_A[NB * 1048576];
__device__ float g_B[NB * 1048576];
__device__ float g_stats[NB * 64 * 2];
__device__ float g_part[262144];                     // per-(b,tile,c) partial (sum,sumsq)
__device__ unsigned char g_wimg[(size_t)NB * SAMP];  // per-sample fp16 weight images

// ---------------- helpers ----------------
__device__ __forceinline__ uint16_t f2h(float v) {
    uint16_t r; asm("cvt.rn.f16.f32 %0, %1;" : "=h"(r) : "f"(v)); return r;
}
__device__ __forceinline__ uint32_t cvt2h(float hi, float lo) {
    uint32_t r; asm("cvt.rn.f16x2.f32 %0, %1, %2;" : "=r"(r) : "f"(hi), "f"(lo)); return r;
}
__device__ __forceinline__ void mma16816(float* c, uint32_t a0, uint32_t a1, uint32_t a2, uint32_t a3,
                                         uint32_t b0, uint32_t b1) {
    asm volatile("mma.sync.aligned.m16n8k16.row.col.f32.f16.f16.f32 "
        "{%0,%1,%2,%3}, {%4,%5,%6,%7}, {%8,%9}, {%0,%1,%2,%3};"
        : "+f"(c[0]), "+f"(c[1]), "+f"(c[2]), "+f"(c[3])
        : "r"(a0), "r"(a1), "r"(a2), "r"(a3), "r"(b0), "r"(b1));
}

// ---------------- merged weight generation ----------------
__global__ void gen_all(const float* __restrict__ W1, const float* __restrict__ B1,
                        const float* __restrict__ W2, const float* __restrict__ B2,
                        const float* __restrict__ W3, const float* __restrict__ B3,
                        const float* __restrict__ W4, const float* __restrict__ B4,
                        const float* __restrict__ W5, const float* __restrict__ B5,
                        const float* __restrict__ W6, const float* __restrict__ B6,
                        const float* __restrict__ W7, const float* __restrict__ B7,
                        const float* __restrict__ act) {
    __shared__ float sa[NB * 32];
    for (int i = threadIdx.x; i < NB * 32; i += blockDim.x) sa[i] = act[i];
    __syncthreads();
    int r = blockIdx.x * blockDim.x + threadIdx.x;
    if (r >= WTOT) return;
    const float* Wt; const float* bt; int local;
    if      (r < 3200)   { Wt = W1; bt = B1; local = r; }
    else if (r < 9600)   { Wt = W2; bt = B2; local = r - 3200; }
    else if (r < 22400)  { Wt = W3; bt = B3; local = r - 9600; }
    else if (r < 48000)  { Wt = W4; bt = B4; local = r - 22400; }
    else if (r < 99200)  { Wt = W5; bt = B5; local = r - 48000; }
    else if (r < 201600) { Wt = W6; bt = B6; local = r - 99200; }
    else                 { Wt = W7; bt = B7; local = r - 201600; }
    float w[32];
    const float4* wp = reinterpret_cast<const float4*>(Wt + (size_t)local * 32);
#pragma unroll
    for (int i = 0; i < 8; i++) { float4 v = wp[i]; w[4*i]=v.x; w[4*i+1]=v.y; w[4*i+2]=v.z; w[4*i+3]=v.w; }
    float bv = bt[local];
    for (int s = 0; s < NB; s++) {
        float acc = bv;
#pragma unroll
        for (int k = 0; k < 32; k++) acc = fmaf(w[k], sa[s*32+k], acc);
        g_y[(size_t)s * WTOT + r] = acc;
    }
}

// ---------------- merged weight image prep (fp16) --------------------------
__global__ void prep_all() {
    int e = blockIdx.x * 256 + threadIdx.x;
    int b = blockIdx.y;
    if (e >= 226944) return;
    if (e >= 223200) {                       // conv1 paired image
        e -= 223200;
        int chunk = e / 288; int rem = e - chunk * 288;
        int cout = rem / 18, kk = rem - cout * 18;
        float v = 0.f;
        if (kk < 16) {
            int tap = 2 * chunk + (kk >> 3);
            int ch = kk & 7;
            if (tap < 25)
                v = g_y[(size_t)b * WTOT + ((size_t)cout * 8 + ch) * 25 + tap];
        }
        *(uint16_t*)(g_wimg + (size_t)b * SAMP + 446400
                     + (size_t)chunk * 576 + ((size_t)cout * 18 + kk) * 2) = f2h(v);
        return;
    }
    int wOff, Cout, CinReal, imgOff;
    if      (e < 14400)  { wOff = 9600;   Cout = 32; CinReal = 16; imgOff = 0;      }
    else if (e < 43200)  { wOff = 22400;  Cout = 32; CinReal = 32; imgOff = 28800;  e -= 14400; }
    else if (e < 100800) { wOff = 48000;  Cout = 64; CinReal = 32; imgOff = 86400;  e -= 43200; }
    else if (e < 216000) { wOff = 99200;  Cout = 64; CinReal = 64; imgOff = 201600; e -= 100800; }
    else                 { wOff = 3200;   Cout = 16; CinReal = 16; imgOff = 432000; e -= 216000; }
    int per = 25 * Cout * 18;
    int chunk = e / per; int rem = e - chunk * per;
    int tap = rem / (Cout * 18); int rem2 = rem - tap * Cout * 18;
    int cout = rem2 / 18; int cc = rem2 - cout * 18;
    int cin = chunk * 16 + cc;
    float v = 0.f;
    if (cc < 16 && cin < CinReal)
        v = g_y[(size_t)b * WTOT + wOff + ((size_t)cout * CinReal + cin) * 25 + tap];
    size_t base = (size_t)b * SAMP + imgOff + (size_t)chunk * (25 * Cout * 36)
                + ((size_t)(tap * Cout + cout) * 18 + cc) * 2;
    *(uint16_t*)(g_wimg + base) = f2h(v);
}

// ---------------- BN stats (layer 0 on x only) ----------------
__global__ void bn_stats(const float* __restrict__ src, const float* __restrict__ g,
                         const float* __restrict__ be, int C, int HW) {
    int plane = blockIdx.x;
    int c = plane % C;
    const float* p = src + (size_t)plane * HW;
    float s = 0.f, s2 = 0.f;
    for (int i = threadIdx.x; i < HW; i += 256) { float v = p[i]; s += v; s2 = fmaf(v, v, s2); }
    __shared__ float sh0[256], sh1[256];
    sh0[threadIdx.x] = s; sh1[threadIdx.x] = s2;
    __syncthreads();
    for (int ofs = 128; ofs > 0; ofs >>= 1) {
        if (threadIdx.x < ofs) { sh0[threadIdx.x] += sh0[threadIdx.x+ofs]; sh1[threadIdx.x] += sh1[threadIdx.x+ofs]; }
        __syncthreads();
    }
    if (threadIdx.x == 0) {
        float inv = 1.f / (float)HW;
        float m = sh0[0] * inv;
        float var = sh1[0] * inv - m * m;
        float sc = g[c] * rsqrtf(var + 1e-5f);
        g_stats[plane*2] = sc;
        g_stats[plane*2+1] = be[c] - m * sc;
    }
}

// ---------------- BN finalize: reduce per-tile partials (deterministic) ----
__global__ void bn_finalize(const float* __restrict__ gamma, const float* __restrict__ beta,
                            int C, int NT, float invHW) {
    int idx = blockIdx.x * 256 + threadIdx.x;
    if (idx >= NB * C) return;
    int b = idx / C, c = idx - b * C;
    float s = 0.f, q = 0.f;
    for (int tIdx = 0; tIdx < NT; tIdx++) {
        const float* p = g_part + (((size_t)b * NT + tIdx) * C + c) * 2;
        s += p[0]; q += p[1];
    }
    float m = s * invHW;
    float var = q * invHW - m * m;
    float sc = gamma[c] * rsqrtf(var + 1e-5f);
    g_stats[idx*2]   = sc;
    g_stats[idx*2+1] = beta[c] - m * sc;
}

// ---------------- stats epilogue (shared by all mma convs) -----------------
// acc[T][NN][4]; lanes = g*4+t. Writes per-tile per-channel (sum, sumsq).
template<int T, int NN, int COUT>
__device__ __forceinline__ void stats_epilogue(float (*acc)[NN][4], char* dsm,
                                               int tid, int w, int lane, int t,
                                               int b, int tile, int nt) {
    float st[NN][4];
#pragma unroll
    for (int n = 0; n < NN; n++) {
        float s0=0.f,q0=0.f,s1=0.f,q1=0.f;
#pragma unroll
        for (int i = 0; i < T; i++) {
            float a0=acc[i][n][0], a1=acc[i][n][1], a2=acc[i][n][2], a3=acc[i][n][3];
            s0 += a0 + a2; q0 = fmaf(a0,a0,fmaf(a2,a2,q0));
            s1 += a1 + a3; q1 = fmaf(a1,a1,fmaf(a3,a3,q1));
        }
        st[n][0]=s0; st[n][1]=q0; st[n][2]=s1; st[n][3]=q1;
    }
#pragma unroll
    for (int n = 0; n < NN; n++)
#pragma unroll
        for (int j = 0; j < 4; j++) {
            st[n][j] += __shfl_xor_sync(0xffffffffu, st[n][j], 4);
            st[n][j] += __shfl_xor_sync(0xffffffffu, st[n][j], 8);
            st[n][j] += __shfl_xor_sync(0xffffffffu, st[n][j], 16);
        }
    float* sred = (float*)dsm;
    __syncthreads();
    if (lane < 4) {
#pragma unroll
        for (int n = 0; n < NN; n++)
#pragma unroll
            for (int j = 0; j < 4; j++)
                sred[((w * NN + n) * 4 + t) * 4 + j] = st[n][j];
    }
    __syncthreads();
    if (tid < NN * 16) {
        int n = tid >> 4, tt = (tid >> 2) & 3, j = tid & 3;
        float s = 0.f;
#pragma unroll
        for (int ww = 0; ww < 8; ww++) s += sred[((ww * NN + n) * 4 + tt) * 4 + j];
        int c = n * 8 + 2 * tt + (j >> 1);
        g_part[(((size_t)b * nt + tile) * COUT + c) * 2 + (j & 1)] = s;
    }
}

// ---------------- mma.sync conv (convs 2-6), x-tiled, fused stats ----------
template<int DIL, int MODE, int CIN, int CREAL, int COUT, int S, int XTILE, int POOL>
__global__ __launch_bounds__(256)
void conv_mma(const float* __restrict__ in, float* __restrict__ out, int imgOff) {
    constexpr int WB = 25 * COUT * 36;
    constexpr int NC = CIN / 16;
    constexpr int XP = XTILE + 4 * DIL;
    constexpr int R  = 4 + 4 * DIL;
    constexpr int PS0 = R * XP;
    constexpr int PSTRIDE = PS0 + ((40 - (PS0 & 31)) & 31);
    constexpr int T  = XTILE / 32;
    constexpr int NN = COUT / 8;
    constexpr int NXT = S / XTILE;
    extern __shared__ __align__(16) char dsm[];
    uint32_t* sStage = (uint32_t*)(dsm + WB);
    const int tid = threadIdx.x, w = tid >> 5, lane = tid & 31;
    const int g = lane >> 2, t = lane & 3;
    const int b = blockIdx.y;
    const int xt = blockIdx.x % NXT, yt = blockIdx.x / NXT;
    const int y0 = yt * 4, x0 = xt * XTILE;
    const int ry = w >> 1, xseg = (w & 1) * (XTILE / 2);
    float acc[T][NN][4];
#pragma unroll
    for (int i = 0; i < T; i++)
#pragma unroll
        for (int n = 0; n < NN; n++)
#pragma unroll
            for (int j = 0; j < 4; j++) acc[i][n][j] = 0.f;
    const unsigned char* img = g_wimg + (size_t)b * SAMP + imgOff;

#pragma unroll 1
    for (int chunk = 0; chunk < NC; chunk++) {
        __syncthreads();
        {
            const uint4* src = (const uint4*)(img + (size_t)chunk * WB);
            uint4* dst = (uint4*)dsm;
            for (int i = tid; i < WB / 16; i += 256) dst[i] = src[i];
        }
        {
            int cb = chunk * 16;
            for (int idx = tid; idx < 8 * PS0; idx += 256) {
                int p = idx / PS0, rem = idx - p * PS0;
                int r = rem / XP, xp = rem - r * XP;
                int iy = y0 + r - 2 * DIL, ix = x0 + xp - 2 * DIL;
                int c0 = cb + p * 2;
                float v0 = 0.f, v1 = 0.f;
                if (iy >= 0 && iy < S && ix >= 0 && ix < S && c0 < CREAL) {
                    const float* bp = in + ((size_t)(b * CREAL + c0)) * (S * S) + (size_t)iy * S + ix;
                    v0 = bp[0]; v1 = bp[(size_t)S * S];
                    if (MODE) {
                        v0 = fmaf(v0, g_stats[(b*CREAL+c0)*2],   g_stats[(b*CREAL+c0)*2+1]);
                        v1 = fmaf(v1, g_stats[(b*CREAL+c0+1)*2], g_stats[(b*CREAL+c0+1)*2+1]);
                        if (MODE == 2) { v0 = fmaxf(v0, 0.f); v1 = fmaxf(v1, 0.f); }
                    }
                }
                uint32_t hp = cvt2h(v1, v0);
                __half2 hh = *reinterpret_cast<__half2*>(&hp);
                float2 bk = __half22float2(hh);
                uint32_t lp = cvt2h(v1 - bk.y, v0 - bk.x);
                sStage[p * PSTRIDE + rem]       = hp;
                sStage[(8 + p) * PSTRIDE + rem] = lp;
            }
        }
        __syncthreads();
#pragma unroll 1
        for (int ky = 0; ky < 5; ky++) {
#pragma unroll 1
            for (int kx = 0; kx < 5; kx++) {
                int off = (ry + ky * DIL) * XP + xseg + kx * DIL + g;
                uint32_t ah[T][4], al[T][4];
#pragma unroll
                for (int i = 0; i < T; i++) {
                    int o = off + i * 16;
                    ah[i][0] = sStage[t * PSTRIDE + o];
                    ah[i][1] = sStage[t * PSTRIDE + o + 8];
                    ah[i][2] = sStage[(t + 4) * PSTRIDE + o];
                    ah[i][3] = sStage[(t + 4) * PSTRIDE + o + 8];
                    al[i][0] = sStage[(t + 8) * PSTRIDE + o];
                    al[i][1] = sStage[(t + 8) * PSTRIDE + o + 8];
                    al[i][2] = sStage[(t + 12) * PSTRIDE + o];
                    al[i][3] = sStage[(t + 12) * PSTRIDE + o + 8];
                }
                const char* wB = dsm + ((ky * 5 + kx) * COUT + g) * 36 + t * 4;
                uint32_t bb[NN][2];
#pragma unroll
                for (int n = 0; n < NN; n++) {
                    bb[n][0] = *(const uint32_t*)(wB + n * 288);
                    bb[n][1] = *(const uint32_t*)(wB + n * 288 + 16);
                }
#pragma unroll
                for (int n = 0; n < NN; n++)
#pragma unroll
                    for (int i = 0; i < T; i++)
                        mma16816(acc[i][n], ah[i][0], ah[i][1], ah[i][2], ah[i][3], bb[n][0], bb[n][1]);
#pragma unroll
                for (int n = 0; n < NN; n++)
#pragma unroll
                    for (int i = 0; i < T; i++)
                        mma16816(acc[i][n], al[i][0], al[i][1], al[i][2], al[i][3], bb[n][0], bb[n][1]);
            }
        }
    }
    if (!POOL) {
        int row = y0 + ry;
        float* orow = out + ((size_t)b * COUT) * (S * S) + (size_t)row * S;
#pragma unroll
        for (int i = 0; i < T; i++) {
            int px = x0 + xseg + i * 16 + g;
#pragma unroll
            for (int n = 0; n < NN; n++) {
                float* p0 = orow + ((size_t)(n * 8 + 2 * t)) * (S * S);
                float* p1 = p0 + (size_t)S * S;
                p0[px]     = acc[i][n][0];
                p1[px]     = acc[i][n][1];
                p0[px + 8] = acc[i][n][2];
                p1[px + 8] = acc[i][n][3];
            }
        }
    }
    // fused BN stats (on raw conv output)
    stats_epilogue<T, NN, COUT>(acc, dsm, tid, w, lane, t, b, blockIdx.x, gridDim.x);
    if (POOL) {
        // dump tile to smem, 2x2 avg, write pooled raw output only
        float* pbuf = (float*)(dsm + WB);
#pragma unroll
        for (int i = 0; i < T; i++) {
            int col = xseg + i * 16 + g;
#pragma unroll
            for (int n = 0; n < NN; n++) {
                int c0 = n * 8 + 2 * t;
                pbuf[c0 * (4 * XTILE) + ry * XTILE + col]           = acc[i][n][0];
                pbuf[(c0 + 1) * (4 * XTILE) + ry * XTILE + col]     = acc[i][n][1];
                pbuf[c0 * (4 * XTILE) + ry * XTILE + col + 8]       = acc[i][n][2];
                pbuf[(c0 + 1) * (4 * XTILE) + ry * XTILE + col + 8] = acc[i][n][3];
            }
        }
        __syncthreads();
        for (int k = tid; k < COUT * 2 * (XTILE / 2); k += 256) {
            int c = k / (2 * (XTILE / 2));
            int rem = k - c * 2 * (XTILE / 2);
            int pr = rem / (XTILE / 2), pc = rem - pr * (XTILE / 2);
            const float* pb = pbuf + c * (4 * XTILE);
            float v = 0.25f * (pb[(2*pr) * XTILE + 2*pc] + pb[(2*pr) * XTILE + 2*pc + 1]
                             + pb[(2*pr+1) * XTILE + 2*pc] + pb[(2*pr+1) * XTILE + 2*pc + 1]);
            out[((size_t)(b * COUT + c)) * ((S/2)*(S/2)) + (size_t)(y0/2 + pr) * (S/2) + (x0/2 + pc)] = v;
        }
    }
}

// ---------------- conv1: tap-paired k16 (8 real channels x 2 taps) ---------
__global__ __launch_bounds__(256)
void conv1_mma(const float* __restrict__ in, float* __restrict__ out, int imgOff) {
    constexpr int S = 256, XTILE = 128, XP = 136, PS0 = 12 * 136;
    constexpr int PSTRIDE = 1640, T = 4, NN = 2;
    extern __shared__ __align__(16) char dsm[];
    uint32_t* sStage = (uint32_t*)(dsm + 7488);
    const int tid = threadIdx.x, w = tid >> 5, lane = tid & 31;
    const int g = lane >> 2, t = lane & 3;
    const int b = blockIdx.y;
    const int xt = blockIdx.x & 1, yt = blockIdx.x >> 1;
    const int y0 = yt * 4, x0 = xt * XTILE;
    const int ry = w >> 1, xseg = (w & 1) * 64;
    float acc[T][NN][4];
#pragma unroll
    for (int i = 0; i < T; i++)
#pragma unroll
        for (int n = 0; n < NN; n++)
#pragma unroll
            for (int j = 0; j < 4; j++) acc[i][n][j] = 0.f;
    const unsigned char* img = g_wimg + (size_t)b * SAMP + imgOff;
    {
        const uint4* src = (const uint4*)img;
        uint4* dst = (uint4*)dsm;
        for (int i = tid; i < 468; i += 256) dst[i] = src[i];
    }
    {
        for (int idx = tid; idx < 4 * PS0; idx += 256) {
            int p = idx / PS0, rem = idx - p * PS0;
            int r = rem / XP, xp = rem - r * XP;
            int iy = y0 + r - 4, ix = x0 + xp - 4;
            int c0 = p * 2;
            float v0 = 0.f, v1 = 0.f;
            if (iy >= 0 && iy < S && ix >= 0 && ix < S) {
                const float* bp = in + ((size_t)(b * 8 + c0)) * 65536 + (size_t)iy * S + ix;
                v0 = bp[0]; v1 = bp[65536];
                v0 = fmaf(v0, g_stats[(b*8+c0)*2],   g_stats[(b*8+c0)*2+1]);
                v1 = fmaf(v1, g_stats[(b*8+c0+1)*2], g_stats[(b*8+c0+1)*2+1]);
            }
            uint32_t hp = cvt2h(v1, v0);
            __half2 hh = *reinterpret_cast<__half2*>(&hp);
            float2 bk = __half22float2(hh);
            uint32_t lp = cvt2h(v1 - bk.y, v0 - bk.x);
            sStage[p * PSTRIDE + rem]       = hp;
            sStage[(4 + p) * PSTRIDE + rem] = lp;
        }
    }
    __syncthreads();
#pragma unroll 1
    for (int q = 0; q < 13; q++) {
        int tap1 = 2 * q, tap2 = (2 * q + 1 < 25) ? 2 * q + 1 : 24;
        int ky1 = tap1 / 5, kx1 = tap1 - ky1 * 5;
        int ky2 = tap2 / 5, kx2 = tap2 - ky2 * 5;
        int o1 = (ry + ky1 * 2) * XP + xseg + kx1 * 2 + g;
        int o2 = (ry + ky2 * 2) * XP + xseg + kx2 * 2 + g;
        uint32_t ah[T][4], al[T][4];
#pragma unroll
        for (int i = 0; i < T; i++) {
            int p1 = o1 + i * 16, p2 = o2 + i * 16;
            ah[i][0] = sStage[t * PSTRIDE + p1];
            ah[i][1] = sStage[t * PSTRIDE + p1 + 8];
            ah[i][2] = sStage[t * PSTRIDE + p2];
            ah[i][3] = sStage[t * PSTRIDE + p2 + 8];
            al[i][0] = sStage[(t + 4) * PSTRIDE + p1];
            al[i][1] = sStage[(t + 4) * PSTRIDE + p1 + 8];
            al[i][2] = sStage[(t + 4) * PSTRIDE + p2];
            al[i][3] = sStage[(t + 4) * PSTRIDE + p2 + 8];
        }
        const char* wB = dsm + (q * 16 + g) * 36 + t * 4;
        uint32_t bb[NN][2];
#pragma unroll
        for (int n = 0; n < NN; n++) {
            bb[n][0] = *(const uint32_t*)(wB + n * 288);
            bb[n][1] = *(const uint32_t*)(wB + n * 288 + 16);
        }
#pragma unroll
        for (int n = 0; n < NN; n++)
#pragma unroll
            for (int i = 0; i < T; i++)
                mma16816(acc[i][n], ah[i][0], ah[i][1], ah[i][2], ah[i][3], bb[n][0], bb[n][1]);
#pragma unroll
        for (int n = 0; n < NN; n++)
#pragma unroll
            for (int i = 0; i < T; i++)
                mma16816(acc[i][n], al[i][0], al[i][1], al[i][2], al[i][3], bb[n][0], bb[n][1]);
    }
    int row = y0 + ry;
    float* orow = out + ((size_t)b * 16) * 65536 + (size_t)row * S;
#pragma unroll
    for (int i = 0; i < T; i++) {
        int px = x0 + xseg + i * 16 + g;
#pragma unroll
        for (int n = 0; n < NN; n++) {
            float* p0 = orow + ((size_t)(n * 8 + 2 * t)) * 65536;
            float* p1 = p0 + 65536;
            p0[px]     = acc[i][n][0];
            p1[px]     = acc[i][n][1];
            p0[px + 8] = acc[i][n][2];
            p1[px + 8] = acc[i][n][3];
        }
    }
    stats_epilogue<T, NN, 16>(acc, dsm, tid, w, lane, t, b, blockIdx.x, gridDim.x);
}

// ---------------- 1x1 conv / upsample+softmax ----------------
__global__ void conv1x1(const float* __restrict__ in, float* __restrict__ out) {
    __shared__ float sw[512];
    int b = blockIdx.y;
    const float* wb = g_y + (size_t)b * WTOT + 201600;
    for (int i = threadIdx.x; i < 512; i += blockDim.x) sw[i] = wb[i];
    __syncthreads();
    int pix = blockIdx.x * blockDim.x + threadIdx.x;
    if (pix >= 16384) return;
    float acc[8] = {0,0,0,0,0,0,0,0};
    for (int c = 0; c < 64; c++) {
        float v = in[((size_t)(b*64 + c)) * 16384 + pix];
        v = fmaf(v, g_stats[(b*64+c)*2], g_stats[(b*64+c)*2+1]);
#pragma unroll
        for (int o = 0; o < 8; o++) acc[o] = fmaf(v, sw[o*64 + c], acc[o]);
    }
#pragma unroll
    for (int o = 0; o < 8; o++) out[((size_t)(b*8 + o)) * 16384 + pix] = acc[o];
}

__global__ void up_softmax(const float* __restrict__ in, float* __restrict__ out) {
    int idx = blockIdx.x * blockDim.x + threadIdx.x;
    if (idx >= NB * 65536) return;
    int x = idx & 255, y = (idx >> 8) & 255, b = idx >> 16;
    const float r = 127.0f / 255.0f;
    float sy = y * r, sx = x * r;
    int y0 = (int)sy, x0 = (int)sx;
    int y1 = min(y0 + 1, 127), x1 = min(x0 + 1, 127);
    float wy = sy - (float)y0, wx = sx - (float)x0;
    const float* bp = in + (size_t)b * 8 * 16384;
    float v[8], m = -1e30f;
#pragma unroll
    for (int o = 0; o < 8; o++) {
        const float* p = bp + o * 16384;
        float a00 = p[y0*128+x0], a01 = p[y0*128+x1];
        float a10 = p[y1*128+x0], a11 = p[y1*128+x1];
        float t0 = a00 * (1.f - wy) + a10 * wy;
        float t1 = a01 * (1.f - wy) + a11 * wy;
        v[o] = t0 * (1.f - wx) + t1 * wx;
        m = fmaxf(m, v[o]);
    }
    float s = 0.f;
#pragma unroll
    for (int o = 0; o < 8; o++) { v[o] = expf(v[o] - m); s += v[o]; }
    float invs = 1.f / s;
    size_t base = ((size_t)b * 8) * 65536 + (size_t)y * 256 + x;
#pragma unroll
    for (int o = 0; o < 8; o++) out[base + (size_t)o * 65536] = v[o] * invs;
}

// ---------------------------------------------------------------------------
extern "C" void kernel_launch(void* const* d_in, const int* in_sizes, int n_in,
                              void* d_out, int out_size) {
    const float* x   = (const float*)d_in[0];
    const float* act = (const float*)d_in[1];
    const float* g[7]; const float* be[7];
    for (int i = 0; i < 7; i++) { g[i] = (const float*)d_in[16 + 2*i]; be[i] = (const float*)d_in[17 + 2*i]; }
    float* out = (float*)d_out;
    float *pA = nullptr, *pB = nullptr;
    cudaGetSymbolAddress((void**)&pA, g_A);
    cudaGetSymbolAddress((void**)&pB, g_B);

    const int SM1 = 7488  + 8  * 1640 * 4;
    const int SM2 = 14400 + 16 * 1064 * 4;
    const int SM3 = 28800 + 16 * 872  * 4;
    const int SM4 = 28800 + 16 * 552  * 4;
    const int SM5 = 57600 + 16 * 872  * 4;
    const int SM6 = 57600 + 16 * 552  * 4;
    cudaFuncSetAttribute(conv1_mma, cudaFuncAttributeMaxDynamicSharedMemorySize, SM1);
    cudaFuncSetAttribute(conv_mma<1,2,16,16,16,256,128,1>, cudaFuncAttributeMaxDynamicSharedMemorySize, SM2);
    cudaFuncSetAttribute(conv_mma<2,1,16,16,32,128,64,0>,  cudaFuncAttributeMaxDynamicSharedMemorySize, SM3);
    cudaFuncSetAttribute(conv_mma<1,2,32,32,32,128,64,0>,  cudaFuncAttributeMaxDynamicSharedMemorySize, SM4);
    cudaFuncSetAttribute(conv_mma<2,1,32,32,64,128,64,0>,  cudaFuncAttributeMaxDynamicSharedMemorySize, SM5);
    cudaFuncSetAttribute(conv_mma<1,2,64,64,64,128,64,0>,  cudaFuncAttributeMaxDynamicSharedMemorySize, SM6);

    gen_all<<<(WTOT + 255) / 256, 256>>>(
        (const float*)d_in[2],  (const float*)d_in[3],
        (const float*)d_in[4],  (const float*)d_in[5],
        (const float*)d_in[6],  (const float*)d_in[7],
        (const float*)d_in[8],  (const float*)d_in[9],
        (const float*)d_in[10], (const float*)d_in[11],
        (const float*)d_in[12], (const float*)d_in[13],
        (const float*)d_in[14], (const float*)d_in[15], act);
    prep_all<<<dim3((226944 + 255) / 256, NB), 256>>>();

    bn_stats<<<NB * 8, 256>>>(x, g[0], be[0], 8, 65536);
    conv1_mma<<<dim3(128, NB), 256, SM1>>>(x, pA, 446400);
    bn_finalize<<<(NB*16 + 255)/256, 256>>>(g[1], be[1], 16, 128, 1.f/65536.f);
    conv_mma<1,2,16,16,16,256,128,1><<<dim3(128, NB), 256, SM2>>>(pA, pB, 432000);   // conv2 + pool
    bn_finalize<<<(NB*16 + 255)/256, 256>>>(g[2], be[2], 16, 128, 1.f/65536.f);
    conv_mma<2,1,16,16,32,128,64,0><<<dim3(64, NB), 256, SM3>>>(pB, pA, 0);          // conv3 (bn2 folded)
    bn_finalize<<<(NB*32 + 255)/256, 256>>>(g[3], be[3], 32, 64, 1.f/16384.f);
    conv_mma<1,2,32,32,32,128,64,0><<<dim3(64, NB), 256, SM4>>>(pA, pB, 28800);      // conv4
    bn_finalize<<<(NB*32 + 255)/256, 256>>>(g[4], be[4], 32, 64, 1.f/16384.f);
    conv_mma<2,1,32,32,64,128,64,0><<<dim3(64, NB), 256, SM5>>>(pB, pA, 86400);      // conv5
    bn_finalize<<<(NB*64 + 255)/256, 256>>>(g[5], be[5], 64, 64, 1.f/16384.f);
    conv_mma<1,2,64,64,64,128,64,0><<<dim3(64, NB), 256, SM6>>>(pA, pB, 201600);     // conv6
    bn_finalize<<<(NB*64 + 255)/256, 256>>>(g[6], be[6], 64, 64, 1.f/16384.f);

    conv1x1<<<dim3(64, NB), 256>>>(pB, pA);
    up_softmax<<<(NB * 65536 + 255) / 256, 256>>>(pA, out);
}